// round 14
// baseline (speedup 1.0000x reference)
#include <cuda_runtime.h>
#include <cuda_bf16.h>
#include <math.h>

typedef unsigned int u32;
typedef unsigned long long u64;

#define NN 10000
#define NE 50000
#define IN_CH 32
#define EIN 16
#define GIN 8
#define HID 64
#define NG 64
#define EPS_BN 1e-5f

#define NODE_G 68
#define MPAD 96
#define ECAP 384
#define EWMAX 24
#define ASTRIDE 200
#define QSTRIDE 136

// ---------------- device scratch ----------------
__device__ __align__(16) __nv_bfloat16 g_Wbf[8192 * 192]; // [j=c*64+o][3K pack hi|lo|hi], stride 192
__device__ float g_Ht [(size_t)128 * NE];  // H transposed, perm-ordered: [c][p]
__device__ float g_xA[NN * HID];
__device__ float g_xB[NN * HID];
__device__ float g_agg[NN * HID];
__device__ float g_xb [NN * HID];
__device__ int   g_off[NN + 1];
__device__ int   g_perm[NE];
__device__ int   g_psrc[NE];
__device__ int   g_pdst[NE];
__device__ float g_bnsum[HID];
__device__ float g_bnsq [HID];
__device__ float g_pool[NG * HID];

// ---------------- PTX helpers ----------------
__device__ __forceinline__ u32 smem_u32(const void* p) {
    u32 a;
    asm("{ .reg .u64 t; cvta.to.shared.u64 t, %1; cvt.u32.u64 %0, t; }" : "=r"(a) : "l"(p));
    return a;
}
__device__ __forceinline__ void ldsm_x4(u32& r0, u32& r1, u32& r2, u32& r3, u32 addr) {
    asm volatile("ldmatrix.sync.aligned.m8n8.x4.shared.b16 {%0,%1,%2,%3}, [%4];"
                 : "=r"(r0), "=r"(r1), "=r"(r2), "=r"(r3) : "r"(addr));
}
__device__ __forceinline__ void ldsm_x2(u32& r0, u32& r1, u32 addr) {
    asm volatile("ldmatrix.sync.aligned.m8n8.x2.shared.b16 {%0,%1}, [%2];"
                 : "=r"(r0), "=r"(r1) : "r"(addr));
}
__device__ __forceinline__ void mma16816(float* c, const u32* a, const u32* b) {
    asm volatile(
        "mma.sync.aligned.m16n8k16.row.col.f32.bf16.bf16.f32 "
        "{%0,%1,%2,%3}, {%4,%5,%6,%7}, {%8,%9}, {%0,%1,%2,%3};"
        : "+f"(c[0]), "+f"(c[1]), "+f"(c[2]), "+f"(c[3])
        : "r"(a[0]), "r"(a[1]), "r"(a[2]), "r"(a[3]), "r"(b[0]), "r"(b[1]));
}
__device__ __forceinline__ void cpasync16(u32 saddr, const void* gaddr) {
    asm volatile("cp.async.ca.shared.global [%0], [%1], 16;" :: "r"(saddr), "l"(gaddr) : "memory");
}
__device__ __forceinline__ void cpasync4(u32 saddr, const void* gaddr) {
    asm volatile("cp.async.ca.shared.global [%0], [%1], 4;" :: "r"(saddr), "l"(gaddr) : "memory");
}
__device__ __forceinline__ void cp_commit() {
    asm volatile("cp.async.commit_group;" ::: "memory");
}
__device__ __forceinline__ void cp_wait0() {
    asm volatile("cp.async.wait_group 0;" ::: "memory");
}

// ---------------- mono CSR: zero + count + scan + scatter, one block ----------------
__global__ void k_csr(const int* __restrict__ src, const int* __restrict__ dst) {
    extern __shared__ int csm[];
    int* scnt = csm;             // NN
    int* scur = csm + NN;        // NN
    int* part = csm + 2 * NN;    // 1024
    int t = threadIdx.x;         // 1024
    for (int i = t; i < NN; i += 1024) scnt[i] = 0;
    __syncthreads();
    for (int e = t; e < NE; e += 1024) atomicAdd(&scnt[src[e]], 1);
    __syncthreads();
    const int CH = (NN + 1023) / 1024;
    int base = t * CH;
    int s = 0;
    for (int i = 0; i < CH; i++) {
        int idx = base + i;
        if (idx < NN) s += scnt[idx];
    }
    part[t] = s;
    __syncthreads();
    for (int d = 1; d < 1024; d <<= 1) {
        int v = (t >= d) ? part[t - d] : 0;
        __syncthreads();
        part[t] += v;
        __syncthreads();
    }
    int pre = (t == 0) ? 0 : part[t - 1];
    for (int i = 0; i < CH; i++) {
        int idx = base + i;
        if (idx < NN) {
            g_off[idx] = pre;
            scur[idx] = pre;
            pre += scnt[idx];
        }
    }
    if (t == 1023) g_off[NN] = part[1023];
    __syncthreads();
    for (int e = t; e < NE; e += 1024) {
        int sv = src[e];
        int p = atomicAdd(&scur[sv], 1);
        g_perm[p] = e;
        g_psrc[p] = sv;
        g_pdst[p] = dst[e];
    }
}

// ---------------- W2 split, coalesced via SMEM transpose ----------------
__global__ void k_wsplit2(const float* __restrict__ w2, int K) {
    __shared__ float ws[64 * 65];
    int c = blockIdx.x;
    int t = threadIdx.x;  // 256
    for (int idx = t; idx < K * 64; idx += 256) {
        int k = idx >> 6, o = idx & 63;
        ws[k * 65 + o] = w2[(size_t)c * (K * 64) + idx];
    }
    __syncthreads();
    int wid = t >> 5, lane = t & 31;
    int np = (3 * K) >> 1;
    u32* Wr = (u32*)g_Wbf;
    for (int o = wid; o < 64; o += 8) {
        size_t j = (size_t)(c * 64 + o);
        for (int pc = lane; pc < np; pc += 32) {
            int j2 = pc * 2;
            int b = j2 / K, kk = j2 - b * K;
            float v0 = ws[kk * 65 + o];
            float v1 = ws[(kk + 1) * 65 + o];
            __nv_bfloat16 h0 = __float2bfloat16(v0);
            __nv_bfloat16 h1 = __float2bfloat16(v1);
            u32 pk;
            if (b == 1) {
                __nv_bfloat16 l0 = __float2bfloat16(v0 - __bfloat162float(h0));
                __nv_bfloat16 l1 = __float2bfloat16(v1 - __bfloat162float(h1));
                pk = (u32)__bfloat16_as_ushort(l0) | ((u32)__bfloat16_as_ushort(l1) << 16);
            } else {
                pk = (u32)__bfloat16_as_ushort(h0) | ((u32)__bfloat16_as_ushort(h1) << 16);
            }
            Wr[j * 96 + pc] = pk;
        }
    }
}

// ---------------- merged edge_h + node_pre (+ bn zero) ----------------
#define EPB 32
#define NEB ((NE + EPB - 1) / EPB)     // 1563 edge blocks
__global__ void k_ehnp(const float* __restrict__ ea,
                       const float* __restrict__ w1,
                       const float* __restrict__ b1,
                       const float* __restrict__ x, int C,
                       const float* __restrict__ root,
                       const float* __restrict__ bias,
                       const float* __restrict__ b2) {
    __shared__ __align__(16) char sm[33792];
    int t = threadIdx.x;  // 256
    if (blockIdx.x < NEB) {
        // ---------- edge_h role: H transposed perm-ordered ----------
        float* ws  = (float*)sm;                 // 2048 f
        float* eas = ws + 2048;                  // 32*17 f
        int*   es  = (int*)(eas + EPB * 17);     // 32
        float* Hs  = (float*)(es + 32);          // 128*33 f
        int p0 = blockIdx.x * EPB;
        int pe = min(EPB, NE - p0);
        for (int idx = t; idx < EIN * 128; idx += 256) ws[idx] = w1[idx];
        if (t < pe) es[t] = g_perm[p0 + t];
        __syncthreads();
        for (int idx = t; idx < pe * EIN; idx += 256) {
            int ei = idx >> 4, i = idx & 15;
            eas[ei * 17 + i] = ea[(size_t)es[ei] * EIN + i];
        }
        __syncthreads();
        if (t < 128) {
            int c = t;
            float b = b1[c];
            for (int ei = 0; ei < pe; ei++) {
                float s = b;
#pragma unroll
                for (int i = 0; i < EIN; i++) s += eas[ei * 17 + i] * ws[i * 128 + c];
                Hs[c * (EPB + 1) + ei] = fmaxf(s, 0.f);
            }
        }
        __syncthreads();
        for (int idx = t; idx < 128 * EPB; idx += 256) {
            int cc = idx >> 5, ei = idx & 31;
            if (ei < pe) g_Ht[(size_t)cc * NE + p0 + ei] = Hs[cc * (EPB + 1) + ei];
        }
    } else {
        // ---------- node_pre role ----------
        int nb = blockIdx.x - NEB;
        float* rs  = (float*)sm;        // 4096 f
        float* b2s = rs + 4096;         // 4096 f
        float* xs  = b2s + 4096;        // 4*64 f
        if (nb == 0 && t < 64) { g_bnsum[t] = 0.f; g_bnsq[t] = 0.f; }
        int o = t & 63, s = t >> 6;
        for (int i = t; i < C * 64; i += 256) { rs[i] = root[i]; b2s[i] = b2[i]; }
        int n = nb * 4 + s;
        if (n < NN) {
            for (int k = o; k < C; k += 64) xs[s * 64 + k] = x[(size_t)n * C + k];
        }
        __syncthreads();
        if (n < NN) {
            float a = bias[o], xbv = 0.f;
            for (int k = 0; k < C; k++) {
                float xv = xs[s * 64 + k];
                a   += xv * rs [k * 64 + o];
                xbv += xv * b2s[k * 64 + o];
            }
            g_agg[n * 64 + o] = a;
            g_xb [n * 64 + o] = xbv;
        }
    }
}

// ---------------- FUSED (exact R10): mma + register-resident edge accumulation ----------------
#define FB_BS 38400
#define FB_QS 89600
#define FB_HS 126592
#define FB_SL 138880
#define FB_TOTAL 140416

template<int K>
__global__ void __launch_bounds__(512, 1) k_fused(const float* __restrict__ X) {
    constexpr int NK16 = (3 * K) / 16;
    constexpr int HALF = K / 2;
    constexpr int NQ   = NK16 * 2;
    extern __shared__ char smem[];
    __nv_bfloat16* As = (__nv_bfloat16*)smem;
    float* Qs = (float*)(smem + FB_QS);
    float* hs = (float*)(smem + FB_HS);
    int*   sl = (int*)(smem + FB_SL);

    int t = threadIdx.x, w = t >> 5, lane = t & 31;
    int n0 = blockIdx.x * NODE_G;
    int nend = min(n0 + NODE_G, NN);
    int p0 = g_off[n0];
    int p1 = g_off[nend];
    int ce = p1 - p0;
    if (ce <= 0) return;
    int ceM = min(ce, ECAP);
    int EW = (ceM + 15) >> 4;
    int eBase = w * EW;

    u32 a_base = smem_u32(As);
    u32 b_base = smem_u32(smem + FB_BS);
    u32 h_base = smem_u32(hs);

    {
        const char* Wsrc = (const char*)g_Wbf;
        for (int i = t; i < 128 * NQ; i += 512) {
            int r = i / NQ, q = i - r * NQ;
            cpasync16(b_base + (u32)(r * 400 + q * 16), Wsrc + (size_t)r * 384 + q * 16);
        }
        for (int i = t; i < 2 * ceM; i += 512) {
            int c01 = (i >= ceM) ? 1 : 0;
            int e = i - c01 * ceM;
            cpasync4(h_base + (u32)((c01 * ECAP + e) * 4),
                     g_Ht + (size_t)c01 * NE + p0 + e);
        }
        cp_commit();
    }

    for (int idx = t; idx < MPAD * HALF; idx += 512) {
        int r = idx / HALF, kp = idx - r * HALF;
        int k = kp * 2;
        int n = n0 + r;
        float v0 = 0.f, v1 = 0.f;
        if (r < NODE_G && n < NN) {
            v0 = X[(size_t)n * K + k];
            v1 = X[(size_t)n * K + k + 1];
        }
        __nv_bfloat16 h0 = __float2bfloat16(v0);
        __nv_bfloat16 h1 = __float2bfloat16(v1);
        __nv_bfloat16 l0 = __float2bfloat16(v0 - __bfloat162float(h0));
        __nv_bfloat16 l1 = __float2bfloat16(v1 - __bfloat162float(h1));
        u32 hp = (u32)__bfloat16_as_ushort(h0) | ((u32)__bfloat16_as_ushort(h1) << 16);
        u32 lp = (u32)__bfloat16_as_ushort(l0) | ((u32)__bfloat16_as_ushort(l1) << 16);
        u32* Arow = (u32*)As + r * 100;
        Arow[kp]            = hp;
        Arow[HALF + kp]     = hp;
        Arow[2 * HALF + kp] = lp;
    }
    for (int i = t; i < ceM; i += 512) sl[i] = g_psrc[p0 + i] - n0;

    int wm = (w & 1) * 48;
    int wn = (w >> 1) * 16;

    float2 eacc[EWMAX];
#pragma unroll
    for (int j = 0; j < EWMAX; j++) eacc[j] = make_float2(0.f, 0.f);

    for (int cb = 0; cb < 64; cb++) {
        int buf = cb & 1;
        cp_wait0();
        __syncthreads();

        float acc[3][2][4];
#pragma unroll
        for (int mi = 0; mi < 3; mi++)
#pragma unroll
            for (int jb = 0; jb < 2; jb++)
#pragma unroll
                for (int q = 0; q < 4; q++) acc[mi][jb][q] = 0.f;
#pragma unroll
        for (int ks = 0; ks < NK16; ks++) {
            int k0 = ks * 16;
            u32 a[3][4];
#pragma unroll
            for (int mi = 0; mi < 3; mi++) {
                u32 addr = a_base + (u32)(((wm + mi * 16 + (lane & 15)) * ASTRIDE +
                                            k0 + (lane >> 4) * 8) * 2);
                ldsm_x4(a[mi][0], a[mi][1], a[mi][2], a[mi][3], addr);
            }
            u32 b[2][2];
#pragma unroll
            for (int jb = 0; jb < 2; jb++) {
                u32 addr = b_base + (u32)(((wn + jb * 8 + (lane & 7)) * ASTRIDE +
                                            k0 + ((lane >> 3) & 1) * 8) * 2);
                ldsm_x2(b[jb][0], b[jb][1], addr);
            }
#pragma unroll
            for (int mi = 0; mi < 3; mi++)
#pragma unroll
                for (int jb = 0; jb < 2; jb++)
                    mma16816(acc[mi][jb], a[mi], b[jb]);
        }
        __syncthreads();

        if (cb < 63) {
            const char* Wn = (const char*)g_Wbf + (size_t)(cb + 1) * 128 * 384;
            for (int i = t; i < 128 * NQ; i += 512) {
                int r = i / NQ, q = i - r * NQ;
                cpasync16(b_base + (u32)(r * 400 + q * 16), Wn + (size_t)r * 384 + q * 16);
            }
            const float* Hn = g_Ht + (size_t)(2 * (cb + 1)) * NE + p0;
            u32 hdst = h_base + (u32)((buf ^ 1) * 2 * ECAP * 4);
            for (int i = t; i < 2 * ceM; i += 512) {
                int c01 = (i >= ceM) ? 1 : 0;
                int e = i - c01 * ceM;
                cpasync4(hdst + (u32)((c01 * ECAP + e) * 4), Hn + (size_t)c01 * NE + e);
            }
        }
        cp_commit();

#pragma unroll
        for (int mi = 0; mi < 3; mi++) {
            int m0 = wm + mi * 16 + (lane >> 2);
#pragma unroll
            for (int jb = 0; jb < 2; jb++) {
                int col = wn + jb * 8 + (lane & 3) * 2;
                if (m0 < NODE_G)
                    *(float2*)&Qs[m0 * QSTRIDE + col] = make_float2(acc[mi][jb][0], acc[mi][jb][1]);
                if (m0 + 8 < NODE_G)
                    *(float2*)&Qs[(m0 + 8) * QSTRIDE + col] = make_float2(acc[mi][jb][2], acc[mi][jb][3]);
            }
        }
        __syncthreads();

        {
            const float* hb0 = hs + buf * 2 * ECAP;
            const float* hb1 = hb0 + ECAP;
#pragma unroll
            for (int j = 0; j < EWMAX; j++) {
                int e = eBase + j;
                if (j < EW && e < ceM) {
                    int s = sl[e];
                    float h0 = hb0[e];
                    float h1 = hb1[e];
                    float2 q0 = *(const float2*)&Qs[s * QSTRIDE + 2 * lane];
                    float2 q1 = *(const float2*)&Qs[s * QSTRIDE + 64 + 2 * lane];
                    eacc[j].x += h0 * q0.x + h1 * q1.x;
                    eacc[j].y += h0 * q0.y + h1 * q1.y;
                }
            }
        }
        for (int e = ceM + w; e < ce; e += 16) {
            int p = p0 + e;
            float h0 = g_Ht[(size_t)(2 * cb) * NE + p];
            float h1 = g_Ht[(size_t)(2 * cb + 1) * NE + p];
            int sg = g_psrc[p];
            int s = sg - n0;
            int d = g_pdst[p];
            float2 q0 = *(const float2*)&Qs[s * QSTRIDE + 2 * lane];
            float2 q1 = *(const float2*)&Qs[s * QSTRIDE + 64 + 2 * lane];
            float ax = h0 * q0.x + h1 * q1.x;
            float ay = h0 * q0.y + h1 * q1.y;
            if (cb == 0) {
                ax += g_xb[(size_t)sg * 64 + 2 * lane];
                ay += g_xb[(size_t)sg * 64 + 2 * lane + 1];
            }
            atomicAdd(&g_agg[(size_t)d * 64 + 2 * lane], ax);
            atomicAdd(&g_agg[(size_t)d * 64 + 2 * lane + 1], ay);
        }
    }

#pragma unroll
    for (int j = 0; j < EWMAX; j++) {
        int e = eBase + j;
        if (j < EW && e < ceM) {
            int p = p0 + e;
            int d = g_pdst[p];
            int sg = n0 + sl[e];
            float2 xv = *(const float2*)&g_xb[(size_t)sg * 64 + 2 * lane];
            atomicAdd(&g_agg[(size_t)d * 64 + 2 * lane],     eacc[j].x + xv.x);
            atomicAdd(&g_agg[(size_t)d * 64 + 2 * lane + 1], eacc[j].y + xv.y);
        }
    }
}

// ---------------- batch norm ----------------
__global__ void k_bn_stats() {
    int t = threadIdx.x;
    int o = t & 63, s = t >> 6;
    float sum = 0.f, sq = 0.f;
    for (int n = blockIdx.x * 4 + s; n < NN; n += gridDim.x * 4) {
        float v = g_agg[(size_t)n * 64 + o];
        sum += v; sq += v * v;
    }
    __shared__ float ssum[256], ssq[256];
    ssum[t] = sum; ssq[t] = sq;
    __syncthreads();
    if (t < 128) { ssum[t] += ssum[t + 128]; ssq[t] += ssq[t + 128]; }
    __syncthreads();
    if (t < 64) {
        atomicAdd(&g_bnsum[t], ssum[t] + ssum[t + 64]);
        atomicAdd(&g_bnsq [t], ssq [t] + ssq [t + 64]);
    }
}
__global__ void k_bn_apply(const float* __restrict__ gamma,
                           const float* __restrict__ beta,
                           float* __restrict__ xout) {
    int i = blockIdx.x * blockDim.x + threadIdx.x;
    if (i >= NN * 64) return;
    int o = i & 63;
    float mu  = g_bnsum[o] * (1.f / NN);
    float var = g_bnsq[o] * (1.f / NN) - mu * mu;
    float v = gamma[o] * (g_agg[i] - mu) * rsqrtf(var + EPS_BN) + beta[o];
    xout[i] = fmaxf(v, 0.f);
}

// ---------------- pooling + final MLP ----------------
__global__ void k_pool_init() {
    int i = blockIdx.x * blockDim.x + threadIdx.x;
    if (i < NG * HID) g_pool[i] = 0.f;
}
__global__ void k_pool(const float* __restrict__ xl, const int* __restrict__ batch) {
    int i = blockIdx.x * blockDim.x + threadIdx.x;
    if (i >= NN * 64) return;
    int n = i >> 6, o = i & 63;
    int g = batch[n];
    atomicMax(reinterpret_cast<unsigned int*>(&g_pool[g * 64 + o]), __float_as_uint(xl[i]));
}
__global__ void k_final(const float* __restrict__ u,
                        const float* __restrict__ w1, const float* __restrict__ b1,
                        const float* __restrict__ w2, const float* __restrict__ b2,
                        float* __restrict__ out) {
    int g = blockIdx.x;
    int j = threadIdx.x;
    __shared__ float cat[72];
    __shared__ float red[64];
    if (j < 64) cat[j] = g_pool[g * 64 + j];
    if (j < 8)  cat[64 + j] = u[g * 8 + j];
    __syncthreads();
    float h = b1[j];
#pragma unroll
    for (int k = 0; k < 72; k++) h += cat[k] * w1[k * 64 + j];
    h = fmaxf(h, 0.f);
    red[j] = h * w2[j];
    __syncthreads();
    for (int s = 32; s > 0; s >>= 1) {
        if (j < s) red[j] += red[j + s];
        __syncthreads();
    }
    if (j == 0) out[g] = red[0] + b2[0];
}

// ---------------- host ----------------
extern "C" void kernel_launch(void* const* d_in, const int* in_sizes, int n_in,
                              void* d_out, int out_size) {
    const float* x       = (const float*)d_in[0];
    const int*   ei      = (const int*)  d_in[1];
    const float* ea      = (const float*)d_in[2];
    const int*   batch   = (const int*)  d_in[3];
    const float* u       = (const float*)d_in[4];
    const float* enn0_w1 = (const float*)d_in[5];
    const float* enn0_b1 = (const float*)d_in[6];
    const float* enn0_w2 = (const float*)d_in[7];
    const float* enn0_b2 = (const float*)d_in[8];
    const float* root0   = (const float*)d_in[9];
    const float* bias0   = (const float*)d_in[10];
    const float* gamma0  = (const float*)d_in[11];
    const float* beta0   = (const float*)d_in[12];
    const float* enn_w1  = (const float*)d_in[13];
    const float* enn_b1  = (const float*)d_in[14];
    const float* enn_w2  = (const float*)d_in[15];
    const float* enn_b2  = (const float*)d_in[16];
    const float* root_l  = (const float*)d_in[17];
    const float* bias_l  = (const float*)d_in[18];
    const float* gamma_l = (const float*)d_in[19];
    const float* beta_l  = (const float*)d_in[20];
    const float* pp_w1   = (const float*)d_in[21];
    const float* pp_b1   = (const float*)d_in[22];
    const float* pp_w2   = (const float*)d_in[23];
    const float* pp_b2   = (const float*)d_in[24];

    const int* src  = ei;
    const int* dste = ei + NE;

    const int CSR_SMEM = (2 * NN + 1024) * 4;   // 84096
    cudaFuncSetAttribute(k_csr, cudaFuncAttributeMaxDynamicSharedMemorySize, CSR_SMEM);
    cudaFuncSetAttribute(k_fused<IN_CH>, cudaFuncAttributeMaxDynamicSharedMemorySize, FB_TOTAL);
    cudaFuncSetAttribute(k_fused<HID>,  cudaFuncAttributeMaxDynamicSharedMemorySize, FB_TOTAL);

    void* pA; cudaGetSymbolAddress(&pA, g_xA);
    void* pB; cudaGetSymbolAddress(&pB, g_xB);
    float* xA = (float*)pA;
    float* xB = (float*)pB;

    // launch 0: mono CSR
    k_csr<<<1, 1024, CSR_SMEM>>>(src, dste);

    const float* xin = x;
    float* xout = xA;

    const int EHNP_GRID = NEB + (NN + 3) / 4;   // 1563 + 2500

    for (int l = 0; l < 4; l++) {
        const float *w1, *b1, *w2, *b2, *rt, *bs, *gm, *bt;
        int C = (l == 0) ? IN_CH : HID;
        if (l == 0) {
            w1 = enn0_w1; b1 = enn0_b1; w2 = enn0_w2; b2 = enn0_b2;
            rt = root0; bs = bias0; gm = gamma0; bt = beta0;
        } else {
            int m = l - 1;
            w1 = enn_w1 + (size_t)m * EIN * 128;
            b1 = enn_b1 + (size_t)m * 128;
            w2 = enn_w2 + (size_t)m * 128 * 4096;
            b2 = enn_b2 + (size_t)m * 4096;
            rt = root_l + (size_t)m * 64 * 64;
            bs = bias_l + (size_t)m * 64;
            gm = gamma_l + (size_t)m * 64;
            bt = beta_l + (size_t)m * 64;
        }
        // launches 1,2 (layer 0): wsplit, ehnp ; launch 3: fused (ncu capture target)
        k_wsplit2<<<128, 256>>>(w2, C);
        k_ehnp   <<<EHNP_GRID, 256>>>(ea, w1, b1, xin, C, rt, bs, b2);
        if (l == 0) k_fused<IN_CH><<<148, 512, FB_TOTAL>>>(xin);
        else        k_fused<HID> <<<148, 512, FB_TOTAL>>>(xin);
        k_bn_stats<<<128, 256>>>();
        k_bn_apply<<<(NN * 64 + 255) / 256, 256>>>(gm, bt, xout);

        xin = xout;
        xout = (xout == xA) ? xB : xA;
    }

    k_pool_init<<<(NG * HID + 255) / 256, 256>>>();
    k_pool     <<<(NN * 64 + 255) / 256, 256>>>(xin, batch);
    k_final    <<<NG, 64>>>(u, pp_w1, pp_b1, pp_w2, pp_b2, (float*)d_out);
}

// round 15
// speedup vs baseline: 1.0369x; 1.0369x over previous
#include <cuda_runtime.h>
#include <cuda_bf16.h>
#include <math.h>

typedef unsigned int u32;
typedef unsigned long long u64;

#define NN 10000
#define NE 50000
#define IN_CH 32
#define EIN 16
#define GIN 8
#define HID 64
#define NG 64
#define EPS_BN 1e-5f

#define NODE_G 68
#define MPAD 96
#define ECAP 384
#define EWMAX 24
#define ASTRIDE 200
#define QSTRIDE 136

// ---------------- device scratch ----------------
__device__ __align__(16) __nv_bfloat16 g_Wbf[8192 * 192];
__device__ float g_Ht [(size_t)128 * NE];
__device__ float g_xA[NN * HID];
__device__ float g_xB[NN * HID];
__device__ float g_agg[NN * HID];
__device__ float g_xb [NN * HID];
__device__ int   g_cnt[NN];
__device__ int   g_off[NN + 1];
__device__ int   g_cur[NN];
__device__ int   g_perm[NE];
__device__ int   g_psrc[NE];
__device__ int   g_pdst[NE];
__device__ float g_bnsum[HID];
__device__ float g_bnsq [HID];
__device__ float g_pool[NG * HID];

// ---------------- PTX helpers ----------------
__device__ __forceinline__ u32 smem_u32(const void* p) {
    u32 a;
    asm("{ .reg .u64 t; cvta.to.shared.u64 t, %1; cvt.u32.u64 %0, t; }" : "=r"(a) : "l"(p));
    return a;
}
__device__ __forceinline__ void ldsm_x4(u32& r0, u32& r1, u32& r2, u32& r3, u32 addr) {
    asm volatile("ldmatrix.sync.aligned.m8n8.x4.shared.b16 {%0,%1,%2,%3}, [%4];"
                 : "=r"(r0), "=r"(r1), "=r"(r2), "=r"(r3) : "r"(addr));
}
__device__ __forceinline__ void ldsm_x2(u32& r0, u32& r1, u32 addr) {
    asm volatile("ldmatrix.sync.aligned.m8n8.x2.shared.b16 {%0,%1}, [%2];"
                 : "=r"(r0), "=r"(r1) : "r"(addr));
}
__device__ __forceinline__ void mma16816(float* c, const u32* a, const u32* b) {
    asm volatile(
        "mma.sync.aligned.m16n8k16.row.col.f32.bf16.bf16.f32 "
        "{%0,%1,%2,%3}, {%4,%5,%6,%7}, {%8,%9}, {%0,%1,%2,%3};"
        : "+f"(c[0]), "+f"(c[1]), "+f"(c[2]), "+f"(c[3])
        : "r"(a[0]), "r"(a[1]), "r"(a[2]), "r"(a[3]), "r"(b[0]), "r"(b[1]));
}
__device__ __forceinline__ void cpasync16(u32 saddr, const void* gaddr) {
    asm volatile("cp.async.ca.shared.global [%0], [%1], 16;" :: "r"(saddr), "l"(gaddr) : "memory");
}
__device__ __forceinline__ void cpasync4(u32 saddr, const void* gaddr) {
    asm volatile("cp.async.ca.shared.global [%0], [%1], 4;" :: "r"(saddr), "l"(gaddr) : "memory");
}
__device__ __forceinline__ void cp_commit() {
    asm volatile("cp.async.commit_group;" ::: "memory");
}
__device__ __forceinline__ void cp_wait0() {
    asm volatile("cp.async.wait_group 0;" ::: "memory");
}

// ---------------- CSR build ----------------
__global__ void k_zero_cnt() {
    int i = blockIdx.x * blockDim.x + threadIdx.x;
    if (i < NN) g_cnt[i] = 0;
}
__global__ void k_count(const int* __restrict__ src) {
    int e = blockIdx.x * blockDim.x + threadIdx.x;
    if (e < NE) atomicAdd(&g_cnt[src[e]], 1);
}
__global__ void k_scan() {
    __shared__ int part[1024];
    int t = threadIdx.x;
    const int CH = (NN + 1023) / 1024;
    int base = t * CH;
    int s = 0;
    for (int i = 0; i < CH; i++) {
        int idx = base + i;
        if (idx < NN) s += g_cnt[idx];
    }
    part[t] = s;
    __syncthreads();
    for (int d = 1; d < 1024; d <<= 1) {
        int v = (t >= d) ? part[t - d] : 0;
        __syncthreads();
        part[t] += v;
        __syncthreads();
    }
    int pre = (t == 0) ? 0 : part[t - 1];
    for (int i = 0; i < CH; i++) {
        int idx = base + i;
        if (idx < NN) {
            g_off[idx] = pre;
            g_cur[idx] = pre;
            pre += g_cnt[idx];
        }
    }
    if (t == 1023) g_off[NN] = part[1023];
}
__global__ void k_scatter(const int* __restrict__ src, const int* __restrict__ dst) {
    int e = blockIdx.x * blockDim.x + threadIdx.x;
    if (e < NE) {
        int s = src[e];
        int p = atomicAdd(&g_cur[s], 1);
        g_perm[p] = e;
        g_psrc[p] = s;
        g_pdst[p] = dst[e];
    }
}

// ---------------- W2 split, coalesced via SMEM transpose ----------------
__global__ void k_wsplit2(const float* __restrict__ w2, int K) {
    __shared__ float ws[64 * 65];
    int c = blockIdx.x;
    int t = threadIdx.x;
    for (int idx = t; idx < K * 64; idx += 256) {
        int k = idx >> 6, o = idx & 63;
        ws[k * 65 + o] = w2[(size_t)c * (K * 64) + idx];
    }
    __syncthreads();
    int wid = t >> 5, lane = t & 31;
    int np = (3 * K) >> 1;
    u32* Wr = (u32*)g_Wbf;
    for (int o = wid; o < 64; o += 8) {
        size_t j = (size_t)(c * 64 + o);
        for (int pc = lane; pc < np; pc += 32) {
            int j2 = pc * 2;
            int b = j2 / K, kk = j2 - b * K;
            float v0 = ws[kk * 65 + o];
            float v1 = ws[(kk + 1) * 65 + o];
            __nv_bfloat16 h0 = __float2bfloat16(v0);
            __nv_bfloat16 h1 = __float2bfloat16(v1);
            u32 pk;
            if (b == 1) {
                __nv_bfloat16 l0 = __float2bfloat16(v0 - __bfloat162float(h0));
                __nv_bfloat16 l1 = __float2bfloat16(v1 - __bfloat162float(h1));
                pk = (u32)__bfloat16_as_ushort(l0) | ((u32)__bfloat16_as_ushort(l1) << 16);
            } else {
                pk = (u32)__bfloat16_as_ushort(h0) | ((u32)__bfloat16_as_ushort(h1) << 16);
            }
            Wr[j * 96 + pc] = pk;
        }
    }
}

// ---------------- edge hidden, transposed + perm-ordered: g_Ht[c][p] ----------------
#define EPB 32
__global__ void k_edge_h(const float* __restrict__ ea,
                         const float* __restrict__ w1,
                         const float* __restrict__ b1) {
    __shared__ float ws[EIN * 128];
    __shared__ float eas[EPB][17];
    __shared__ int   es[EPB];
    __shared__ float Hs[128][EPB + 1];
    int t = threadIdx.x;
    int p0 = blockIdx.x * EPB;
    int pe = min(EPB, NE - p0);
    for (int idx = t; idx < EIN * 128; idx += 128) ws[idx] = w1[idx];
    if (t < pe) es[t] = g_perm[p0 + t];
    __syncthreads();
    for (int idx = t; idx < pe * EIN; idx += 128) {
        int ei = idx >> 4, i = idx & 15;
        eas[ei][i] = ea[(size_t)es[ei] * EIN + i];
    }
    __syncthreads();
    int c = t;
    float b = b1[c];
    for (int ei = 0; ei < pe; ei++) {
        float s = b;
#pragma unroll
        for (int i = 0; i < EIN; i++) s += eas[ei][i] * ws[i * 128 + c];
        Hs[c][ei] = fmaxf(s, 0.f);
    }
    __syncthreads();
    for (int idx = t; idx < 128 * EPB; idx += 128) {
        int cc = idx >> 5, ei = idx & 31;
        if (ei < pe) g_Ht[(size_t)cc * NE + p0 + ei] = Hs[cc][ei];
    }
}

// ---------------- node pre ----------------
__global__ void k_node_pre(const float* __restrict__ x, int C,
                           const float* __restrict__ root,
                           const float* __restrict__ bias,
                           const float* __restrict__ b2) {
    __shared__ float xs[4][64];
    __shared__ float rs[64 * 64];
    __shared__ float b2s[64 * 64];
    int t = threadIdx.x;
    int o = t & 63, s = t >> 6;
    for (int i = t; i < C * 64; i += 256) { rs[i] = root[i]; b2s[i] = b2[i]; }
    int n = blockIdx.x * 4 + s;
    if (n < NN) {
        for (int k = o; k < C; k += 64) xs[s][k] = x[(size_t)n * C + k];
    }
    __syncthreads();
    if (n < NN) {
        float a = bias[o], xbv = 0.f;
        for (int k = 0; k < C; k++) {
            float xv = xs[s][k];
            a   += xv * rs [k * 64 + o];
            xbv += xv * b2s[k * 64 + o];
        }
        g_agg[n * 64 + o] = a;
        g_xb [n * 64 + o] = xbv;
    }
}

// ---------------- FUSED v8: R10 + source-dedup in edge phase ----------------
#define FB_BS 38400
#define FB_QS 89600
#define FB_HS 126592
#define FB_SL 138880
#define FB_TOTAL 140416

template<int K>
__global__ void __launch_bounds__(512, 1) k_fused(const float* __restrict__ X) {
    constexpr int NK16 = (3 * K) / 16;
    constexpr int HALF = K / 2;
    constexpr int NQ   = NK16 * 2;
    extern __shared__ char smem[];
    __nv_bfloat16* As = (__nv_bfloat16*)smem;
    float* Qs = (float*)(smem + FB_QS);
    float* hs = (float*)(smem + FB_HS);
    int*   sl = (int*)(smem + FB_SL);

    int t = threadIdx.x, w = t >> 5, lane = t & 31;
    int n0 = blockIdx.x * NODE_G;
    int nend = min(n0 + NODE_G, NN);
    int p0 = g_off[n0];
    int p1 = g_off[nend];
    int ce = p1 - p0;
    if (ce <= 0) return;
    int ceM = min(ce, ECAP);
    int EW = (ceM + 15) >> 4;
    int eBase = w * EW;

    u32 a_base = smem_u32(As);
    u32 b_base = smem_u32(smem + FB_BS);
    u32 h_base = smem_u32(hs);

    {
        const char* Wsrc = (const char*)g_Wbf;
        for (int i = t; i < 128 * NQ; i += 512) {
            int r = i / NQ, q = i - r * NQ;
            cpasync16(b_base + (u32)(r * 400 + q * 16), Wsrc + (size_t)r * 384 + q * 16);
        }
        for (int i = t; i < 2 * ceM; i += 512) {
            int c01 = (i >= ceM) ? 1 : 0;
            int e = i - c01 * ceM;
            cpasync4(h_base + (u32)((c01 * ECAP + e) * 4),
                     g_Ht + (size_t)c01 * NE + p0 + e);
        }
        cp_commit();
    }

    for (int idx = t; idx < MPAD * HALF; idx += 512) {
        int r = idx / HALF, kp = idx - r * HALF;
        int k = kp * 2;
        int n = n0 + r;
        float v0 = 0.f, v1 = 0.f;
        if (r < NODE_G && n < NN) {
            v0 = X[(size_t)n * K + k];
            v1 = X[(size_t)n * K + k + 1];
        }
        __nv_bfloat16 h0 = __float2bfloat16(v0);
        __nv_bfloat16 h1 = __float2bfloat16(v1);
        __nv_bfloat16 l0 = __float2bfloat16(v0 - __bfloat162float(h0));
        __nv_bfloat16 l1 = __float2bfloat16(v1 - __bfloat162float(h1));
        u32 hp = (u32)__bfloat16_as_ushort(h0) | ((u32)__bfloat16_as_ushort(h1) << 16);
        u32 lp = (u32)__bfloat16_as_ushort(l0) | ((u32)__bfloat16_as_ushort(l1) << 16);
        u32* Arow = (u32*)As + r * 100;
        Arow[kp]            = hp;
        Arow[HALF + kp]     = hp;
        Arow[2 * HALF + kp] = lp;
    }
    for (int i = t; i < ceM; i += 512) sl[i] = g_psrc[p0 + i] - n0;

    int wm = (w & 1) * 48;
    int wn = (w >> 1) * 16;

    float2 eacc[EWMAX];
#pragma unroll
    for (int j = 0; j < EWMAX; j++) eacc[j] = make_float2(0.f, 0.f);

    for (int cb = 0; cb < 64; cb++) {
        int buf = cb & 1;
        cp_wait0();
        __syncthreads();

        float acc[3][2][4];
#pragma unroll
        for (int mi = 0; mi < 3; mi++)
#pragma unroll
            for (int jb = 0; jb < 2; jb++)
#pragma unroll
                for (int q = 0; q < 4; q++) acc[mi][jb][q] = 0.f;
#pragma unroll
        for (int ks = 0; ks < NK16; ks++) {
            int k0 = ks * 16;
            u32 a[3][4];
#pragma unroll
            for (int mi = 0; mi < 3; mi++) {
                u32 addr = a_base + (u32)(((wm + mi * 16 + (lane & 15)) * ASTRIDE +
                                            k0 + (lane >> 4) * 8) * 2);
                ldsm_x4(a[mi][0], a[mi][1], a[mi][2], a[mi][3], addr);
            }
            u32 b[2][2];
#pragma unroll
            for (int jb = 0; jb < 2; jb++) {
                u32 addr = b_base + (u32)(((wn + jb * 8 + (lane & 7)) * ASTRIDE +
                                            k0 + ((lane >> 3) & 1) * 8) * 2);
                ldsm_x2(b[jb][0], b[jb][1], addr);
            }
#pragma unroll
            for (int mi = 0; mi < 3; mi++)
#pragma unroll
                for (int jb = 0; jb < 2; jb++)
                    mma16816(acc[mi][jb], a[mi], b[jb]);
        }
        __syncthreads();

        if (cb < 63) {
            const char* Wn = (const char*)g_Wbf + (size_t)(cb + 1) * 128 * 384;
            for (int i = t; i < 128 * NQ; i += 512) {
                int r = i / NQ, q = i - r * NQ;
                cpasync16(b_base + (u32)(r * 400 + q * 16), Wn + (size_t)r * 384 + q * 16);
            }
            const float* Hn = g_Ht + (size_t)(2 * (cb + 1)) * NE + p0;
            u32 hdst = h_base + (u32)((buf ^ 1) * 2 * ECAP * 4);
            for (int i = t; i < 2 * ceM; i += 512) {
                int c01 = (i >= ceM) ? 1 : 0;
                int e = i - c01 * ceM;
                cpasync4(hdst + (u32)((c01 * ECAP + e) * 4), Hn + (size_t)c01 * NE + e);
            }
        }
        cp_commit();

#pragma unroll
        for (int mi = 0; mi < 3; mi++) {
            int m0 = wm + mi * 16 + (lane >> 2);
#pragma unroll
            for (int jb = 0; jb < 2; jb++) {
                int col = wn + jb * 8 + (lane & 3) * 2;
                if (m0 < NODE_G)
                    *(float2*)&Qs[m0 * QSTRIDE + col] = make_float2(acc[mi][jb][0], acc[mi][jb][1]);
                if (m0 + 8 < NODE_G)
                    *(float2*)&Qs[(m0 + 8) * QSTRIDE + col] = make_float2(acc[mi][jb][2], acc[mi][jb][3]);
            }
        }
        __syncthreads();

        // ---- edge phase: register accumulation with source-dedup ----
        {
            const float* hb0 = hs + buf * 2 * ECAP;
            const float* hb1 = hb0 + ECAP;
            int prev = -1;
            float2 q0 = make_float2(0.f, 0.f), q1 = make_float2(0.f, 0.f);
#pragma unroll
            for (int j = 0; j < EWMAX; j++) {
                int e = eBase + j;
                if (j < EW && e < ceM) {
                    int s = sl[e];
                    if (s != prev) {   // warp-uniform branch; edges sorted by src
                        q0 = *(const float2*)&Qs[s * QSTRIDE + 2 * lane];
                        q1 = *(const float2*)&Qs[s * QSTRIDE + 64 + 2 * lane];
                        prev = s;
                    }
                    float h0 = hb0[e];
                    float h1 = hb1[e];
                    eacc[j].x += h0 * q0.x + h1 * q1.x;
                    eacc[j].y += h0 * q0.y + h1 * q1.y;
                }
            }
        }
        for (int e = ceM + w; e < ce; e += 16) {
            int p = p0 + e;
            float h0 = g_Ht[(size_t)(2 * cb) * NE + p];
            float h1 = g_Ht[(size_t)(2 * cb + 1) * NE + p];
            int sg = g_psrc[p];
            int s = sg - n0;
            int d = g_pdst[p];
            float2 q0 = *(const float2*)&Qs[s * QSTRIDE + 2 * lane];
            float2 q1 = *(const float2*)&Qs[s * QSTRIDE + 64 + 2 * lane];
            float ax = h0 * q0.x + h1 * q1.x;
            float ay = h0 * q0.y + h1 * q1.y;
            if (cb == 0) {
                ax += g_xb[(size_t)sg * 64 + 2 * lane];
                ay += g_xb[(size_t)sg * 64 + 2 * lane + 1];
            }
            atomicAdd(&g_agg[(size_t)d * 64 + 2 * lane], ax);
            atomicAdd(&g_agg[(size_t)d * 64 + 2 * lane + 1], ay);
        }
    }

#pragma unroll
    for (int j = 0; j < EWMAX; j++) {
        int e = eBase + j;
        if (j < EW && e < ceM) {
            int p = p0 + e;
            int d = g_pdst[p];
            int sg = n0 + sl[e];
            float2 xv = *(const float2*)&g_xb[(size_t)sg * 64 + 2 * lane];
            atomicAdd(&g_agg[(size_t)d * 64 + 2 * lane],     eacc[j].x + xv.x);
            atomicAdd(&g_agg[(size_t)d * 64 + 2 * lane + 1], eacc[j].y + xv.y);
        }
    }
}

// ---------------- batch norm ----------------
__global__ void k_bn_zero() {
    int t = threadIdx.x;
    if (t < HID) { g_bnsum[t] = 0.f; g_bnsq[t] = 0.f; }
}
__global__ void k_bn_stats() {
    int t = threadIdx.x;
    int o = t & 63, s = t >> 6;
    float sum = 0.f, sq = 0.f;
    for (int n = blockIdx.x * 4 + s; n < NN; n += gridDim.x * 4) {
        float v = g_agg[(size_t)n * 64 + o];
        sum += v; sq += v * v;
    }
    __shared__ float ssum[256], ssq[256];
    ssum[t] = sum; ssq[t] = sq;
    __syncthreads();
    if (t < 128) { ssum[t] += ssum[t + 128]; ssq[t] += ssq[t + 128]; }
    __syncthreads();
    if (t < 64) {
        atomicAdd(&g_bnsum[t], ssum[t] + ssum[t + 64]);
        atomicAdd(&g_bnsq [t], ssq [t] + ssq [t + 64]);
    }
}
__global__ void k_bn_apply(const float* __restrict__ gamma,
                           const float* __restrict__ beta,
                           float* __restrict__ xout) {
    int i = blockIdx.x * blockDim.x + threadIdx.x;
    if (i >= NN * 64) return;
    int o = i & 63;
    float mu  = g_bnsum[o] * (1.f / NN);
    float var = g_bnsq[o] * (1.f / NN) - mu * mu;
    float v = gamma[o] * (g_agg[i] - mu) * rsqrtf(var + EPS_BN) + beta[o];
    xout[i] = fmaxf(v, 0.f);
}

// ---------------- pooling + final MLP ----------------
__global__ void k_pool_init() {
    int i = blockIdx.x * blockDim.x + threadIdx.x;
    if (i < NG * HID) g_pool[i] = 0.f;
}
__global__ void k_pool(const float* __restrict__ xl, const int* __restrict__ batch) {
    int i = blockIdx.x * blockDim.x + threadIdx.x;
    if (i >= NN * 64) return;
    int n = i >> 6, o = i & 63;
    int g = batch[n];
    atomicMax(reinterpret_cast<unsigned int*>(&g_pool[g * 64 + o]), __float_as_uint(xl[i]));
}
__global__ void k_final(const float* __restrict__ u,
                        const float* __restrict__ w1, const float* __restrict__ b1,
                        const float* __restrict__ w2, const float* __restrict__ b2,
                        float* __restrict__ out) {
    int g = blockIdx.x;
    int j = threadIdx.x;
    __shared__ float cat[72];
    __shared__ float red[64];
    if (j < 64) cat[j] = g_pool[g * 64 + j];
    if (j < 8)  cat[64 + j] = u[g * 8 + j];
    __syncthreads();
    float h = b1[j];
#pragma unroll
    for (int k = 0; k < 72; k++) h += cat[k] * w1[k * 64 + j];
    h = fmaxf(h, 0.f);
    red[j] = h * w2[j];
    __syncthreads();
    for (int s = 32; s > 0; s >>= 1) {
        if (j < s) red[j] += red[j + s];
        __syncthreads();
    }
    if (j == 0) out[g] = red[0] + b2[0];
}

// ---------------- host ----------------
extern "C" void kernel_launch(void* const* d_in, const int* in_sizes, int n_in,
                              void* d_out, int out_size) {
    const float* x       = (const float*)d_in[0];
    const int*   ei      = (const int*)  d_in[1];
    const float* ea      = (const float*)d_in[2];
    const int*   batch   = (const int*)  d_in[3];
    const float* u       = (const float*)d_in[4];
    const float* enn0_w1 = (const float*)d_in[5];
    const float* enn0_b1 = (const float*)d_in[6];
    const float* enn0_w2 = (const float*)d_in[7];
    const float* enn0_b2 = (const float*)d_in[8];
    const float* root0   = (const float*)d_in[9];
    const float* bias0   = (const float*)d_in[10];
    const float* gamma0  = (const float*)d_in[11];
    const float* beta0   = (const float*)d_in[12];
    const float* enn_w1  = (const float*)d_in[13];
    const float* enn_b1  = (const float*)d_in[14];
    const float* enn_w2  = (const float*)d_in[15];
    const float* enn_b2  = (const float*)d_in[16];
    const float* root_l  = (const float*)d_in[17];
    const float* bias_l  = (const float*)d_in[18];
    const float* gamma_l = (const float*)d_in[19];
    const float* beta_l  = (const float*)d_in[20];
    const float* pp_w1   = (const float*)d_in[21];
    const float* pp_b1   = (const float*)d_in[22];
    const float* pp_w2   = (const float*)d_in[23];
    const float* pp_b2   = (const float*)d_in[24];

    const int* src  = ei;
    const int* dste = ei + NE;

    cudaFuncSetAttribute(k_fused<IN_CH>, cudaFuncAttributeMaxDynamicSharedMemorySize, FB_TOTAL);
    cudaFuncSetAttribute(k_fused<HID>,  cudaFuncAttributeMaxDynamicSharedMemorySize, FB_TOTAL);

    void* pA; cudaGetSymbolAddress(&pA, g_xA);
    void* pB; cudaGetSymbolAddress(&pB, g_xB);
    float* xA = (float*)pA;
    float* xB = (float*)pB;

    k_zero_cnt<<<(NN + 255) / 256, 256>>>();
    k_count  <<<(NE + 255) / 256, 256>>>(src);
    k_scan   <<<1, 1024>>>();
    k_scatter<<<(NE + 255) / 256, 256>>>(src, dste);

    const float* xin = x;
    float* xout = xA;

    for (int l = 0; l < 4; l++) {
        const float *w1, *b1, *w2, *b2, *rt, *bs, *gm, *bt;
        int C = (l == 0) ? IN_CH : HID;
        if (l == 0) {
            w1 = enn0_w1; b1 = enn0_b1; w2 = enn0_w2; b2 = enn0_b2;
            rt = root0; bs = bias0; gm = gamma0; bt = beta0;
        } else {
            int m = l - 1;
            w1 = enn_w1 + (size_t)m * EIN * 128;
            b1 = enn_b1 + (size_t)m * 128;
            w2 = enn_w2 + (size_t)m * 128 * 4096;
            b2 = enn_b2 + (size_t)m * 4096;
            rt = root_l + (size_t)m * 64 * 64;
            bs = bias_l + (size_t)m * 64;
            gm = gamma_l + (size_t)m * 64;
            bt = beta_l + (size_t)m * 64;
        }
        k_wsplit2 <<<128, 256>>>(w2, C);
        k_edge_h  <<<(NE + EPB - 1) / EPB, 128>>>(ea, w1, b1);
        k_node_pre<<<(NN + 3) / 4, 256>>>(xin, C, rt, bs, b2);
        if (l == 0) k_fused<IN_CH><<<148, 512, FB_TOTAL>>>(xin);
        else        k_fused<HID> <<<148, 512, FB_TOTAL>>>(xin);
        k_bn_zero <<<1, 64>>>();
        k_bn_stats<<<128, 256>>>();
        k_bn_apply<<<(NN * 64 + 255) / 256, 256>>>(gm, bt, xout);

        xin = xout;
        xout = (xout == xA) ? xB : xA;
    }

    k_pool_init<<<(NG * HID + 255) / 256, 256>>>();
    k_pool     <<<(NN * 64 + 255) / 256, 256>>>(xin, batch);
    k_final    <<<NG, 64>>>(u, pp_w1, pp_b1, pp_w2, pp_b2, (float*)d_out);
}

// round 16
// speedup vs baseline: 1.0702x; 1.0320x over previous
#include <cuda_runtime.h>
#include <cuda_bf16.h>
#include <math.h>

typedef unsigned int u32;
typedef unsigned long long u64;

#define NN 10000
#define NE 50000
#define IN_CH 32
#define EIN 16
#define GIN 8
#define HID 64
#define NG 64
#define EPS_BN 1e-5f

#define NODE_G 68
#define MPAD 96
#define ECAP 384
#define EWMAX 24
#define ASTRIDE 200
#define QSTRIDE 136
#define EPB 32
#define NEB ((NE + EPB - 1) / EPB)

// ---------------- device scratch ----------------
__device__ __align__(16) __nv_bfloat16 g_Wbf4[(size_t)4 * 8192 * 192];
__device__ float g_Ht4[(size_t)4 * 128 * NE];
__device__ float g_aggA[NN * HID];
__device__ float g_aggB[NN * HID];
__device__ float g_xb [NN * HID];
__device__ int   g_cnt[NN];
__device__ int   g_off[NN + 1];
__device__ int   g_cur[NN];
__device__ int   g_perm[NE];
__device__ int   g_psrc[NE];
__device__ int   g_pdst[NE];
__device__ float g_bnsum4[4 * 64];
__device__ float g_bnsq4 [4 * 64];
__device__ float g_pool[NG * HID];

// ---------------- PTX helpers ----------------
__device__ __forceinline__ u32 smem_u32(const void* p) {
    u32 a;
    asm("{ .reg .u64 t; cvta.to.shared.u64 t, %1; cvt.u32.u64 %0, t; }" : "=r"(a) : "l"(p));
    return a;
}
__device__ __forceinline__ void ldsm_x4(u32& r0, u32& r1, u32& r2, u32& r3, u32 addr) {
    asm volatile("ldmatrix.sync.aligned.m8n8.x4.shared.b16 {%0,%1,%2,%3}, [%4];"
                 : "=r"(r0), "=r"(r1), "=r"(r2), "=r"(r3) : "r"(addr));
}
__device__ __forceinline__ void ldsm_x2(u32& r0, u32& r1, u32 addr) {
    asm volatile("ldmatrix.sync.aligned.m8n8.x2.shared.b16 {%0,%1}, [%2];"
                 : "=r"(r0), "=r"(r1) : "r"(addr));
}
__device__ __forceinline__ void mma16816(float* c, const u32* a, const u32* b) {
    asm volatile(
        "mma.sync.aligned.m16n8k16.row.col.f32.bf16.bf16.f32 "
        "{%0,%1,%2,%3}, {%4,%5,%6,%7}, {%8,%9}, {%0,%1,%2,%3};"
        : "+f"(c[0]), "+f"(c[1]), "+f"(c[2]), "+f"(c[3])
        : "r"(a[0]), "r"(a[1]), "r"(a[2]), "r"(a[3]), "r"(b[0]), "r"(b[1]));
}
__device__ __forceinline__ void cpasync16(u32 saddr, const void* gaddr) {
    asm volatile("cp.async.ca.shared.global [%0], [%1], 16;" :: "r"(saddr), "l"(gaddr) : "memory");
}
__device__ __forceinline__ void cpasync4(u32 saddr, const void* gaddr) {
    asm volatile("cp.async.ca.shared.global [%0], [%1], 4;" :: "r"(saddr), "l"(gaddr) : "memory");
}
__device__ __forceinline__ void cp_commit() {
    asm volatile("cp.async.commit_group;" ::: "memory");
}
__device__ __forceinline__ void cp_wait0() {
    asm volatile("cp.async.wait_group 0;" ::: "memory");
}
__device__ __forceinline__ float bnrelu(float raw, float ga, float be, float su, float sq) {
    float mu = su * (1.f / NN);
    float va = sq * (1.f / NN) - mu * mu;
    return fmaxf(ga * (raw - mu) * rsqrtf(va + EPS_BN) + be, 0.f);
}

// ---------------- CSR build ----------------
__global__ void k_zero_cnt() {
    int i = blockIdx.x * blockDim.x + threadIdx.x;
    if (i < NN) g_cnt[i] = 0;
}
__global__ void k_count(const int* __restrict__ src) {
    int e = blockIdx.x * blockDim.x + threadIdx.x;
    if (e < NE) atomicAdd(&g_cnt[src[e]], 1);
}
__global__ void k_scan() {
    __shared__ int part[1024];
    int t = threadIdx.x;
    const int CH = (NN + 1023) / 1024;
    int base = t * CH;
    int s = 0;
    for (int i = 0; i < CH; i++) {
        int idx = base + i;
        if (idx < NN) s += g_cnt[idx];
    }
    part[t] = s;
    __syncthreads();
    for (int d = 1; d < 1024; d <<= 1) {
        int v = (t >= d) ? part[t - d] : 0;
        __syncthreads();
        part[t] += v;
        __syncthreads();
    }
    int pre = (t == 0) ? 0 : part[t - 1];
    for (int i = 0; i < CH; i++) {
        int idx = base + i;
        if (idx < NN) {
            g_off[idx] = pre;
            g_cur[idx] = pre;
            pre += g_cnt[idx];
        }
    }
    if (t == 1023) g_off[NN] = part[1023];
}
__global__ void k_scatter(const int* __restrict__ src, const int* __restrict__ dst) {
    int e = blockIdx.x * blockDim.x + threadIdx.x;
    if (e < NE) {
        int s = src[e];
        int p = atomicAdd(&g_cur[s], 1);
        g_perm[p] = e;
        g_psrc[p] = s;
        g_pdst[p] = dst[e];
    }
}

// ---------------- W2 split for ALL layers ----------------
__global__ void k_wsplit_all(const float* __restrict__ w2_0,
                             const float* __restrict__ w2_l) {
    __shared__ float ws[64 * 65];
    int l = blockIdx.x >> 7;
    int c = blockIdx.x & 127;
    int K = (l == 0) ? IN_CH : HID;
    const float* w2 = (l == 0) ? w2_0 : (w2_l + (size_t)(l - 1) * 128 * 4096);
    __nv_bfloat16* Wout = g_Wbf4 + (size_t)l * 8192 * 192;
    int t = threadIdx.x;
    for (int idx = t; idx < K * 64; idx += 256) {
        int k = idx >> 6, o = idx & 63;
        ws[k * 65 + o] = w2[(size_t)c * (K * 64) + idx];
    }
    __syncthreads();
    int wid = t >> 5, lane = t & 31;
    int np = (3 * K) >> 1;
    u32* Wr = (u32*)Wout;
    for (int o = wid; o < 64; o += 8) {
        size_t j = (size_t)(c * 64 + o);
        for (int pc = lane; pc < np; pc += 32) {
            int j2 = pc * 2;
            int b = j2 / K, kk = j2 - b * K;
            float v0 = ws[kk * 65 + o];
            float v1 = ws[(kk + 1) * 65 + o];
            __nv_bfloat16 h0 = __float2bfloat16(v0);
            __nv_bfloat16 h1 = __float2bfloat16(v1);
            u32 pk;
            if (b == 1) {
                __nv_bfloat16 l0 = __float2bfloat16(v0 - __bfloat162float(h0));
                __nv_bfloat16 l1 = __float2bfloat16(v1 - __bfloat162float(h1));
                pk = (u32)__bfloat16_as_ushort(l0) | ((u32)__bfloat16_as_ushort(l1) << 16);
            } else {
                pk = (u32)__bfloat16_as_ushort(h0) | ((u32)__bfloat16_as_ushort(h1) << 16);
            }
            Wr[j * 96 + pc] = pk;
        }
    }
}

// ---------------- edge hidden for ALL layers ----------------
__global__ void k_edgeh_all(const float* __restrict__ ea,
                            const float* __restrict__ w1_0,
                            const float* __restrict__ b1_0,
                            const float* __restrict__ w1_l,
                            const float* __restrict__ b1_l) {
    __shared__ float ws[EIN * 128];
    __shared__ float eas[EPB][17];
    __shared__ int   es[EPB];
    __shared__ float Hs[128][EPB + 1];
    int l = blockIdx.x / NEB;
    int bb = blockIdx.x - l * NEB;
    const float* w1 = (l == 0) ? w1_0 : (w1_l + (size_t)(l - 1) * EIN * 128);
    const float* b1 = (l == 0) ? b1_0 : (b1_l + (size_t)(l - 1) * 128);
    float* Hout = g_Ht4 + (size_t)l * 128 * NE;
    int t = threadIdx.x;   // 128
    int p0 = bb * EPB;
    int pe = min(EPB, NE - p0);
    for (int idx = t; idx < EIN * 128; idx += 128) ws[idx] = w1[idx];
    if (t < pe) es[t] = g_perm[p0 + t];
    __syncthreads();
    for (int idx = t; idx < pe * EIN; idx += 128) {
        int ei = idx >> 4, i = idx & 15;
        eas[ei][i] = ea[(size_t)es[ei] * EIN + i];
    }
    __syncthreads();
    int c = t;
    float b = b1[c];
    for (int ei = 0; ei < pe; ei++) {
        float s = b;
#pragma unroll
        for (int i = 0; i < EIN; i++) s += eas[ei][i] * ws[i * 128 + c];
        Hs[c][ei] = fmaxf(s, 0.f);
    }
    __syncthreads();
    for (int idx = t; idx < 128 * EPB; idx += 128) {
        int cc = idx >> 5, ei = idx & 31;
        if (ei < pe) Hout[(size_t)cc * NE + p0 + ei] = Hs[cc][ei];
    }
}

// ---------------- node pre (BN-inline from prev agg) ----------------
__global__ void k_node_pre(const float* __restrict__ prev, int C, int bnflag,
                           const float* __restrict__ pgam, const float* __restrict__ pbet,
                           const float* __restrict__ psum, const float* __restrict__ psq,
                           float* __restrict__ aggcur,
                           const float* __restrict__ root,
                           const float* __restrict__ bias,
                           const float* __restrict__ b2,
                           float* __restrict__ zsum, float* __restrict__ zsq) {
    __shared__ float xs[4][64];
    __shared__ float rs[64 * 64];
    __shared__ float b2s[64 * 64];
    int t = threadIdx.x;
    if (blockIdx.x == 0 && t < 64) { zsum[t] = 0.f; zsq[t] = 0.f; }
    int o = t & 63, s = t >> 6;
    for (int i = t; i < C * 64; i += 256) { rs[i] = root[i]; b2s[i] = b2[i]; }
    int n = blockIdx.x * 4 + s;
    if (n < NN) {
        for (int k = o; k < C; k += 64) {
            float raw = prev[(size_t)n * C + k];
            if (bnflag) raw = bnrelu(raw, pgam[k], pbet[k], psum[k], psq[k]);
            xs[s][k] = raw;
        }
    }
    __syncthreads();
    if (n < NN) {
        float a = bias[o], xbv = 0.f;
        for (int k = 0; k < C; k++) {
            float xv = xs[s][k];
            a   += xv * rs [k * 64 + o];
            xbv += xv * b2s[k * 64 + o];
        }
        aggcur[n * 64 + o] = a;
        g_xb [n * 64 + o] = xbv;
    }
}

// ---------------- FUSED (R10 + BN-inline A fill) ----------------
#define FB_BS 38400
#define FB_QS 89600
#define FB_HS 126592
#define FB_SL 138880
#define FB_TOTAL 140416

template<int K, bool BN>
__global__ void __launch_bounds__(512, 1) k_fused(
        const float* __restrict__ X,
        const __nv_bfloat16* __restrict__ Wl,
        const float* __restrict__ Htl,
        float* __restrict__ aggout,
        const float* __restrict__ pgam, const float* __restrict__ pbet,
        const float* __restrict__ psum, const float* __restrict__ psq) {
    constexpr int NK16 = (3 * K) / 16;
    constexpr int HALF = K / 2;
    constexpr int NQ   = NK16 * 2;
    extern __shared__ char smem[];
    __nv_bfloat16* As = (__nv_bfloat16*)smem;
    float* Qs = (float*)(smem + FB_QS);
    float* hs = (float*)(smem + FB_HS);
    int*   sl = (int*)(smem + FB_SL);

    int t = threadIdx.x, w = t >> 5, lane = t & 31;
    int n0 = blockIdx.x * NODE_G;
    int nend = min(n0 + NODE_G, NN);
    int p0 = g_off[n0];
    int p1 = g_off[nend];
    int ce = p1 - p0;
    if (ce <= 0) return;
    int ceM = min(ce, ECAP);
    int EW = (ceM + 15) >> 4;
    int eBase = w * EW;

    u32 a_base = smem_u32(As);
    u32 b_base = smem_u32(smem + FB_BS);
    u32 h_base = smem_u32(hs);

    {
        const char* Wsrc = (const char*)Wl;
        for (int i = t; i < 128 * NQ; i += 512) {
            int r = i / NQ, q = i - r * NQ;
            cpasync16(b_base + (u32)(r * 400 + q * 16), Wsrc + (size_t)r * 384 + q * 16);
        }
        for (int i = t; i < 2 * ceM; i += 512) {
            int c01 = (i >= ceM) ? 1 : 0;
            int e = i - c01 * ceM;
            cpasync4(h_base + (u32)((c01 * ECAP + e) * 4),
                     Htl + (size_t)c01 * NE + p0 + e);
        }
        cp_commit();
    }

    for (int idx = t; idx < MPAD * HALF; idx += 512) {
        int r = idx / HALF, kp = idx - r * HALF;
        int k = kp * 2;
        int n = n0 + r;
        float v0 = 0.f, v1 = 0.f;
        if (r < NODE_G && n < NN) {
            v0 = X[(size_t)n * K + k];
            v1 = X[(size_t)n * K + k + 1];
            if (BN) {
                v0 = bnrelu(v0, pgam[k], pbet[k], psum[k], psq[k]);
                v1 = bnrelu(v1, pgam[k + 1], pbet[k + 1], psum[k + 1], psq[k + 1]);
            }
        }
        __nv_bfloat16 h0 = __float2bfloat16(v0);
        __nv_bfloat16 h1 = __float2bfloat16(v1);
        __nv_bfloat16 l0 = __float2bfloat16(v0 - __bfloat162float(h0));
        __nv_bfloat16 l1 = __float2bfloat16(v1 - __bfloat162float(h1));
        u32 hp = (u32)__bfloat16_as_ushort(h0) | ((u32)__bfloat16_as_ushort(h1) << 16);
        u32 lp = (u32)__bfloat16_as_ushort(l0) | ((u32)__bfloat16_as_ushort(l1) << 16);
        u32* Arow = (u32*)As + r * 100;
        Arow[kp]            = hp;
        Arow[HALF + kp]     = hp;
        Arow[2 * HALF + kp] = lp;
    }
    for (int i = t; i < ceM; i += 512) sl[i] = g_psrc[p0 + i] - n0;

    int wm = (w & 1) * 48;
    int wn = (w >> 1) * 16;

    float2 eacc[EWMAX];
#pragma unroll
    for (int j = 0; j < EWMAX; j++) eacc[j] = make_float2(0.f, 0.f);

    for (int cb = 0; cb < 64; cb++) {
        int buf = cb & 1;
        cp_wait0();
        __syncthreads();

        float acc[3][2][4];
#pragma unroll
        for (int mi = 0; mi < 3; mi++)
#pragma unroll
            for (int jb = 0; jb < 2; jb++)
#pragma unroll
                for (int q = 0; q < 4; q++) acc[mi][jb][q] = 0.f;
#pragma unroll
        for (int ks = 0; ks < NK16; ks++) {
            int k0 = ks * 16;
            u32 a[3][4];
#pragma unroll
            for (int mi = 0; mi < 3; mi++) {
                u32 addr = a_base + (u32)(((wm + mi * 16 + (lane & 15)) * ASTRIDE +
                                            k0 + (lane >> 4) * 8) * 2);
                ldsm_x4(a[mi][0], a[mi][1], a[mi][2], a[mi][3], addr);
            }
            u32 b[2][2];
#pragma unroll
            for (int jb = 0; jb < 2; jb++) {
                u32 addr = b_base + (u32)(((wn + jb * 8 + (lane & 7)) * ASTRIDE +
                                            k0 + ((lane >> 3) & 1) * 8) * 2);
                ldsm_x2(b[jb][0], b[jb][1], addr);
            }
#pragma unroll
            for (int mi = 0; mi < 3; mi++)
#pragma unroll
                for (int jb = 0; jb < 2; jb++)
                    mma16816(acc[mi][jb], a[mi], b[jb]);
        }
        __syncthreads();

        if (cb < 63) {
            const char* Wn = (const char*)Wl + (size_t)(cb + 1) * 128 * 384;
            for (int i = t; i < 128 * NQ; i += 512) {
                int r = i / NQ, q = i - r * NQ;
                cpasync16(b_base + (u32)(r * 400 + q * 16), Wn + (size_t)r * 384 + q * 16);
            }
            const float* Hn = Htl + (size_t)(2 * (cb + 1)) * NE + p0;
            u32 hdst = h_base + (u32)((buf ^ 1) * 2 * ECAP * 4);
            for (int i = t; i < 2 * ceM; i += 512) {
                int c01 = (i >= ceM) ? 1 : 0;
                int e = i - c01 * ceM;
                cpasync4(hdst + (u32)((c01 * ECAP + e) * 4), Hn + (size_t)c01 * NE + e);
            }
        }
        cp_commit();

#pragma unroll
        for (int mi = 0; mi < 3; mi++) {
            int m0 = wm + mi * 16 + (lane >> 2);
#pragma unroll
            for (int jb = 0; jb < 2; jb++) {
                int col = wn + jb * 8 + (lane & 3) * 2;
                if (m0 < NODE_G)
                    *(float2*)&Qs[m0 * QSTRIDE + col] = make_float2(acc[mi][jb][0], acc[mi][jb][1]);
                if (m0 + 8 < NODE_G)
                    *(float2*)&Qs[(m0 + 8) * QSTRIDE + col] = make_float2(acc[mi][jb][2], acc[mi][jb][3]);
            }
        }
        __syncthreads();

        {
            const float* hb0 = hs + buf * 2 * ECAP;
            const float* hb1 = hb0 + ECAP;
#pragma unroll
            for (int j = 0; j < EWMAX; j++) {
                int e = eBase + j;
                if (j < EW && e < ceM) {
                    int s = sl[e];
                    float h0 = hb0[e];
                    float h1 = hb1[e];
                    float2 q0 = *(const float2*)&Qs[s * QSTRIDE + 2 * lane];
                    float2 q1 = *(const float2*)&Qs[s * QSTRIDE + 64 + 2 * lane];
                    eacc[j].x += h0 * q0.x + h1 * q1.x;
                    eacc[j].y += h0 * q0.y + h1 * q1.y;
                }
            }
        }
        for (int e = ceM + w; e < ce; e += 16) {
            int p = p0 + e;
            float h0 = Htl[(size_t)(2 * cb) * NE + p];
            float h1 = Htl[(size_t)(2 * cb + 1) * NE + p];
            int sg = g_psrc[p];
            int s = sg - n0;
            int d = g_pdst[p];
            float2 q0 = *(const float2*)&Qs[s * QSTRIDE + 2 * lane];
            float2 q1 = *(const float2*)&Qs[s * QSTRIDE + 64 + 2 * lane];
            float ax = h0 * q0.x + h1 * q1.x;
            float ay = h0 * q0.y + h1 * q1.y;
            if (cb == 0) {
                ax += g_xb[(size_t)sg * 64 + 2 * lane];
                ay += g_xb[(size_t)sg * 64 + 2 * lane + 1];
            }
            atomicAdd(&aggout[(size_t)d * 64 + 2 * lane], ax);
            atomicAdd(&aggout[(size_t)d * 64 + 2 * lane + 1], ay);
        }
    }

#pragma unroll
    for (int j = 0; j < EWMAX; j++) {
        int e = eBase + j;
        if (j < EW && e < ceM) {
            int p = p0 + e;
            int d = g_pdst[p];
            int sg = n0 + sl[e];
            float2 xv = *(const float2*)&g_xb[(size_t)sg * 64 + 2 * lane];
            atomicAdd(&aggout[(size_t)d * 64 + 2 * lane],     eacc[j].x + xv.x);
            atomicAdd(&aggout[(size_t)d * 64 + 2 * lane + 1], eacc[j].y + xv.y);
        }
    }
}

// ---------------- batch norm stats ----------------
__global__ void k_bn_stats(const float* __restrict__ agg,
                           float* __restrict__ bsum, float* __restrict__ bsq) {
    int t = threadIdx.x;
    int o = t & 63, s = t >> 6;
    float sum = 0.f, sq = 0.f;
    for (int n = blockIdx.x * 4 + s; n < NN; n += gridDim.x * 4) {
        float v = agg[(size_t)n * 64 + o];
        sum += v; sq += v * v;
    }
    __shared__ float ssum[256], ssq[256];
    ssum[t] = sum; ssq[t] = sq;
    __syncthreads();
    if (t < 128) { ssum[t] += ssum[t + 128]; ssq[t] += ssq[t + 128]; }
    __syncthreads();
    if (t < 64) {
        atomicAdd(&bsum[t], ssum[t] + ssum[t + 64]);
        atomicAdd(&bsq [t], ssq [t] + ssq [t + 64]);
    }
}

// ---------------- pooling (BN-inline) + final MLP ----------------
__global__ void k_pool_init() {
    int i = blockIdx.x * blockDim.x + threadIdx.x;
    if (i < NG * HID) g_pool[i] = 0.f;
}
__global__ void k_pool(const float* __restrict__ agg,
                       const float* __restrict__ pgam, const float* __restrict__ pbet,
                       const float* __restrict__ psum, const float* __restrict__ psq,
                       const int* __restrict__ batch) {
    int i = blockIdx.x * blockDim.x + threadIdx.x;
    if (i >= NN * 64) return;
    int n = i >> 6, o = i & 63;
    float v = bnrelu(agg[i], pgam[o], pbet[o], psum[o], psq[o]);
    int g = batch[n];
    atomicMax(reinterpret_cast<unsigned int*>(&g_pool[g * 64 + o]), __float_as_uint(v));
}
__global__ void k_final(const float* __restrict__ u,
                        const float* __restrict__ w1, const float* __restrict__ b1,
                        const float* __restrict__ w2, const float* __restrict__ b2,
                        float* __restrict__ out) {
    int g = blockIdx.x;
    int j = threadIdx.x;
    __shared__ float cat[72];
    __shared__ float red[64];
    if (j < 64) cat[j] = g_pool[g * 64 + j];
    if (j < 8)  cat[64 + j] = u[g * 8 + j];
    __syncthreads();
    float h = b1[j];
#pragma unroll
    for (int k = 0; k < 72; k++) h += cat[k] * w1[k * 64 + j];
    h = fmaxf(h, 0.f);
    red[j] = h * w2[j];
    __syncthreads();
    for (int s = 32; s > 0; s >>= 1) {
        if (j < s) red[j] += red[j + s];
        __syncthreads();
    }
    if (j == 0) out[g] = red[0] + b2[0];
}

// ---------------- host ----------------
extern "C" void kernel_launch(void* const* d_in, const int* in_sizes, int n_in,
                              void* d_out, int out_size) {
    const float* x       = (const float*)d_in[0];
    const int*   ei      = (const int*)  d_in[1];
    const float* ea      = (const float*)d_in[2];
    const int*   batch   = (const int*)  d_in[3];
    const float* u       = (const float*)d_in[4];
    const float* enn0_w1 = (const float*)d_in[5];
    const float* enn0_b1 = (const float*)d_in[6];
    const float* enn0_w2 = (const float*)d_in[7];
    const float* enn0_b2 = (const float*)d_in[8];
    const float* root0   = (const float*)d_in[9];
    const float* bias0   = (const float*)d_in[10];
    const float* gamma0  = (const float*)d_in[11];
    const float* beta0   = (const float*)d_in[12];
    const float* enn_w1  = (const float*)d_in[13];
    const float* enn_b1  = (const float*)d_in[14];
    const float* enn_w2  = (const float*)d_in[15];
    const float* enn_b2  = (const float*)d_in[16];
    const float* root_l  = (const float*)d_in[17];
    const float* bias_l  = (const float*)d_in[18];
    const float* gamma_l = (const float*)d_in[19];
    const float* beta_l  = (const float*)d_in[20];
    const float* pp_w1   = (const float*)d_in[21];
    const float* pp_b1   = (const float*)d_in[22];
    const float* pp_w2   = (const float*)d_in[23];
    const float* pp_b2   = (const float*)d_in[24];

    const int* src  = ei;
    const int* dste = ei + NE;

    cudaFuncSetAttribute((void*)k_fused<IN_CH, false>, cudaFuncAttributeMaxDynamicSharedMemorySize, FB_TOTAL);
    cudaFuncSetAttribute((void*)k_fused<HID, true>,    cudaFuncAttributeMaxDynamicSharedMemorySize, FB_TOTAL);

    void* p;
    cudaGetSymbolAddress(&p, g_aggA);   float* aggA = (float*)p;
    cudaGetSymbolAddress(&p, g_aggB);   float* aggB = (float*)p;
    cudaGetSymbolAddress(&p, g_bnsum4); float* bns  = (float*)p;
    cudaGetSymbolAddress(&p, g_bnsq4);  float* bnq  = (float*)p;
    cudaGetSymbolAddress(&p, g_Wbf4);   __nv_bfloat16* Wbf = (__nv_bfloat16*)p;
    cudaGetSymbolAddress(&p, g_Ht4);    float* Ht   = (float*)p;

    // CSR
    k_zero_cnt<<<(NN + 255) / 256, 256>>>();
    k_count  <<<(NE + 255) / 256, 256>>>(src);
    k_scan   <<<1, 1024>>>();
    k_scatter<<<(NE + 255) / 256, 256>>>(src, dste);

    // all-layer preprocessing (input-only)
    k_wsplit_all<<<512, 256>>>(enn0_w2, enn_w2);
    k_edgeh_all <<<4 * NEB, 128>>>(ea, enn0_w1, enn0_b1, enn_w1, enn_b1);

    const float* prev = x;
    const float* pgam = gamma0, *pbet = beta0;   // placeholders for layer 0 (unused)
    float* psum = bns, *psq = bnq;

    for (int l = 0; l < 4; l++) {
        int C = (l == 0) ? IN_CH : HID;
        const float *rt, *bs, *b2;
        if (l == 0) { rt = root0; bs = bias0; b2 = enn0_b2; }
        else {
            int m = l - 1;
            rt = root_l + (size_t)m * 64 * 64;
            bs = bias_l + (size_t)m * 64;
            b2 = enn_b2 + (size_t)m * 4096;
        }
        float* cur = (l & 1) ? aggB : aggA;
        float* sum_l = bns + l * 64;
        float* sq_l  = bnq + l * 64;

        k_node_pre<<<(NN + 3) / 4, 256>>>(prev, C, (l > 0) ? 1 : 0,
                                          pgam, pbet, psum, psq,
                                          cur, rt, bs, b2, sum_l, sq_l);
        __nv_bfloat16* Wl = Wbf + (size_t)l * 8192 * 192;
        float* Htl = Ht + (size_t)l * 128 * NE;
        if (l == 0)
            k_fused<IN_CH, false><<<148, 512, FB_TOTAL>>>(prev, Wl, Htl, cur,
                                                          pgam, pbet, psum, psq);
        else
            k_fused<HID, true><<<148, 512, FB_TOTAL>>>(prev, Wl, Htl, cur,
                                                       pgam, pbet, psum, psq);
        k_bn_stats<<<128, 256>>>(cur, sum_l, sq_l);

        // next-layer BN params = this layer's
        prev = cur;
        if (l == 0) { pgam = gamma0; pbet = beta0; }
        else        { pgam = gamma_l + (size_t)(l - 1) * 64; pbet = beta_l + (size_t)(l - 1) * 64; }
        psum = sum_l; psq = sq_l;
    }

    k_pool_init<<<(NG * HID + 255) / 256, 256>>>();
    k_pool     <<<(NN * 64 + 255) / 256, 256>>>(prev,
                    gamma_l + 2 * 64, beta_l + 2 * 64, bns + 3 * 64, bnq + 3 * 64, batch);
    k_final    <<<NG, 64>>>(u, pp_w1, pp_b1, pp_w2, pp_b2, (float*)d_out);
}

// round 17
// speedup vs baseline: 1.0938x; 1.0221x over previous
#include <cuda_runtime.h>
#include <cuda_bf16.h>
#include <math.h>

typedef unsigned int u32;
typedef unsigned long long u64;

#define NN 10000
#define NE 50000
#define IN_CH 32
#define EIN 16
#define GIN 8
#define HID 64
#define NG 64
#define EPS_BN 1e-5f

#define NODE_G 68
#define MPAD 96
#define ECAP 384
#define HPAD 392      // ECAP + 8, multiple of 4 (16B-aligned rows)
#define EWMAX 24
#define ASTRIDE 200
#define QSTRIDE 136
#define EPB 32
#define NEB ((NE + EPB - 1) / EPB)

// ---------------- device scratch ----------------
__device__ __align__(16) __nv_bfloat16 g_Wbf4[(size_t)4 * 8192 * 192];
__device__ __align__(16) float g_Ht4[(size_t)4 * 128 * NE];
__device__ float g_aggA[NN * HID];
__device__ float g_aggB[NN * HID];
__device__ float g_xb [NN * HID];
__device__ int   g_cnt[NN];
__device__ int   g_off[NN + 1];
__device__ int   g_cur[NN];
__device__ int   g_perm[NE];
__device__ int   g_psrc[NE];
__device__ int   g_pdst[NE];
__device__ float g_bnsum4[4 * 64];
__device__ float g_bnsq4 [4 * 64];
__device__ float g_pool[NG * HID];

// ---------------- PTX helpers ----------------
__device__ __forceinline__ u32 smem_u32(const void* p) {
    u32 a;
    asm("{ .reg .u64 t; cvta.to.shared.u64 t, %1; cvt.u32.u64 %0, t; }" : "=r"(a) : "l"(p));
    return a;
}
__device__ __forceinline__ void ldsm_x4(u32& r0, u32& r1, u32& r2, u32& r3, u32 addr) {
    asm volatile("ldmatrix.sync.aligned.m8n8.x4.shared.b16 {%0,%1,%2,%3}, [%4];"
                 : "=r"(r0), "=r"(r1), "=r"(r2), "=r"(r3) : "r"(addr));
}
__device__ __forceinline__ void ldsm_x2(u32& r0, u32& r1, u32 addr) {
    asm volatile("ldmatrix.sync.aligned.m8n8.x2.shared.b16 {%0,%1}, [%2];"
                 : "=r"(r0), "=r"(r1) : "r"(addr));
}
__device__ __forceinline__ void mma16816(float* c, const u32* a, const u32* b) {
    asm volatile(
        "mma.sync.aligned.m16n8k16.row.col.f32.bf16.bf16.f32 "
        "{%0,%1,%2,%3}, {%4,%5,%6,%7}, {%8,%9}, {%0,%1,%2,%3};"
        : "+f"(c[0]), "+f"(c[1]), "+f"(c[2]), "+f"(c[3])
        : "r"(a[0]), "r"(a[1]), "r"(a[2]), "r"(a[3]), "r"(b[0]), "r"(b[1]));
}
__device__ __forceinline__ void cpasync16(u32 saddr, const void* gaddr) {
    asm volatile("cp.async.ca.shared.global [%0], [%1], 16;" :: "r"(saddr), "l"(gaddr) : "memory");
}
__device__ __forceinline__ void cp_commit() {
    asm volatile("cp.async.commit_group;" ::: "memory");
}
__device__ __forceinline__ void cp_wait0() {
    asm volatile("cp.async.wait_group 0;" ::: "memory");
}
__device__ __forceinline__ float bnrelu(float raw, float ga, float be, float su, float sq) {
    float mu = su * (1.f / NN);
    float va = sq * (1.f / NN) - mu * mu;
    return fmaxf(ga * (raw - mu) * rsqrtf(va + EPS_BN) + be, 0.f);
}

// ---------------- CSR build ----------------
__global__ void k_zero_cnt() {
    int i = blockIdx.x * blockDim.x + threadIdx.x;
    if (i < NN) g_cnt[i] = 0;
}
__global__ void k_count(const int* __restrict__ src) {
    int e = blockIdx.x * blockDim.x + threadIdx.x;
    if (e < NE) atomicAdd(&g_cnt[src[e]], 1);
}
__global__ void k_scan() {
    __shared__ int part[1024];
    int t = threadIdx.x;
    const int CH = (NN + 1023) / 1024;
    int base = t * CH;
    int s = 0;
    for (int i = 0; i < CH; i++) {
        int idx = base + i;
        if (idx < NN) s += g_cnt[idx];
    }
    part[t] = s;
    __syncthreads();
    for (int d = 1; d < 1024; d <<= 1) {
        int v = (t >= d) ? part[t - d] : 0;
        __syncthreads();
        part[t] += v;
        __syncthreads();
    }
    int pre = (t == 0) ? 0 : part[t - 1];
    for (int i = 0; i < CH; i++) {
        int idx = base + i;
        if (idx < NN) {
            g_off[idx] = pre;
            g_cur[idx] = pre;
            pre += g_cnt[idx];
        }
    }
    if (t == 1023) g_off[NN] = part[1023];
}
__global__ void k_scatter(const int* __restrict__ src, const int* __restrict__ dst) {
    int e = blockIdx.x * blockDim.x + threadIdx.x;
    if (e < NE) {
        int s = src[e];
        int p = atomicAdd(&g_cur[s], 1);
        g_perm[p] = e;
        g_psrc[p] = s;
        g_pdst[p] = dst[e];
    }
}

// ---------------- W2 split for ALL layers ----------------
__global__ void k_wsplit_all(const float* __restrict__ w2_0,
                             const float* __restrict__ w2_l) {
    __shared__ float ws[64 * 65];
    int l = blockIdx.x >> 7;
    int c = blockIdx.x & 127;
    int K = (l == 0) ? IN_CH : HID;
    const float* w2 = (l == 0) ? w2_0 : (w2_l + (size_t)(l - 1) * 128 * 4096);
    __nv_bfloat16* Wout = g_Wbf4 + (size_t)l * 8192 * 192;
    int t = threadIdx.x;
    for (int idx = t; idx < K * 64; idx += 256) {
        int k = idx >> 6, o = idx & 63;
        ws[k * 65 + o] = w2[(size_t)c * (K * 64) + idx];
    }
    __syncthreads();
    int wid = t >> 5, lane = t & 31;
    int np = (3 * K) >> 1;
    u32* Wr = (u32*)Wout;
    for (int o = wid; o < 64; o += 8) {
        size_t j = (size_t)(c * 64 + o);
        for (int pc = lane; pc < np; pc += 32) {
            int j2 = pc * 2;
            int b = j2 / K, kk = j2 - b * K;
            float v0 = ws[kk * 65 + o];
            float v1 = ws[(kk + 1) * 65 + o];
            __nv_bfloat16 h0 = __float2bfloat16(v0);
            __nv_bfloat16 h1 = __float2bfloat16(v1);
            u32 pk;
            if (b == 1) {
                __nv_bfloat16 l0 = __float2bfloat16(v0 - __bfloat162float(h0));
                __nv_bfloat16 l1 = __float2bfloat16(v1 - __bfloat162float(h1));
                pk = (u32)__bfloat16_as_ushort(l0) | ((u32)__bfloat16_as_ushort(l1) << 16);
            } else {
                pk = (u32)__bfloat16_as_ushort(h0) | ((u32)__bfloat16_as_ushort(h1) << 16);
            }
            Wr[j * 96 + pc] = pk;
        }
    }
}

// ---------------- edge hidden for ALL layers ----------------
__global__ void k_edgeh_all(const float* __restrict__ ea,
                            const float* __restrict__ w1_0,
                            const float* __restrict__ b1_0,
                            const float* __restrict__ w1_l,
                            const float* __restrict__ b1_l) {
    __shared__ float ws[EIN * 128];
    __shared__ float eas[EPB][17];
    __shared__ int   es[EPB];
    __shared__ float Hs[128][EPB + 1];
    int l = blockIdx.x / NEB;
    int bb = blockIdx.x - l * NEB;
    const float* w1 = (l == 0) ? w1_0 : (w1_l + (size_t)(l - 1) * EIN * 128);
    const float* b1 = (l == 0) ? b1_0 : (b1_l + (size_t)(l - 1) * 128);
    float* Hout = g_Ht4 + (size_t)l * 128 * NE;
    int t = threadIdx.x;   // 128
    int p0 = bb * EPB;
    int pe = min(EPB, NE - p0);
    for (int idx = t; idx < EIN * 128; idx += 128) ws[idx] = w1[idx];
    if (t < pe) es[t] = g_perm[p0 + t];
    __syncthreads();
    for (int idx = t; idx < pe * EIN; idx += 128) {
        int ei = idx >> 4, i = idx & 15;
        eas[ei][i] = ea[(size_t)es[ei] * EIN + i];
    }
    __syncthreads();
    int c = t;
    float b = b1[c];
    for (int ei = 0; ei < pe; ei++) {
        float s = b;
#pragma unroll
        for (int i = 0; i < EIN; i++) s += eas[ei][i] * ws[i * 128 + c];
        Hs[c][ei] = fmaxf(s, 0.f);
    }
    __syncthreads();
    for (int idx = t; idx < 128 * EPB; idx += 128) {
        int cc = idx >> 5, ei = idx & 31;
        if (ei < pe) Hout[(size_t)cc * NE + p0 + ei] = Hs[cc][ei];
    }
}

// ---------------- node pre (BN-inline from prev agg) ----------------
__global__ void k_node_pre(const float* __restrict__ prev, int C, int bnflag,
                           const float* __restrict__ pgam, const float* __restrict__ pbet,
                           const float* __restrict__ psum, const float* __restrict__ psq,
                           float* __restrict__ aggcur,
                           const float* __restrict__ root,
                           const float* __restrict__ bias,
                           const float* __restrict__ b2,
                           float* __restrict__ zsum, float* __restrict__ zsq) {
    __shared__ float xs[4][64];
    __shared__ float rs[64 * 64];
    __shared__ float b2s[64 * 64];
    int t = threadIdx.x;
    if (blockIdx.x == 0 && t < 64) { zsum[t] = 0.f; zsq[t] = 0.f; }
    int o = t & 63, s = t >> 6;
    for (int i = t; i < C * 64; i += 256) { rs[i] = root[i]; b2s[i] = b2[i]; }
    int n = blockIdx.x * 4 + s;
    if (n < NN) {
        for (int k = o; k < C; k += 64) {
            float raw = prev[(size_t)n * C + k];
            if (bnflag) raw = bnrelu(raw, pgam[k], pbet[k], psum[k], psq[k]);
            xs[s][k] = raw;
        }
    }
    __syncthreads();
    if (n < NN) {
        float a = bias[o], xbv = 0.f;
        for (int k = 0; k < C; k++) {
            float xv = xs[s][k];
            a   += xv * rs [k * 64 + o];
            xbv += xv * b2s[k * 64 + o];
        }
        aggcur[n * 64 + o] = a;
        g_xb [n * 64 + o] = xbv;
    }
}

// ---------------- FUSED (R16 + 16B H prefetch) ----------------
#define FB_BS 38400
#define FB_QS 89600
#define FB_HS 126592
#define FB_SL 139136        // FB_HS + 2*2*HPAD*4 = 126592 + 12544
#define FB_TOTAL 140672

template<int K, bool BN>
__global__ void __launch_bounds__(512, 1) k_fused(
        const float* __restrict__ X,
        const __nv_bfloat16* __restrict__ Wl,
        const float* __restrict__ Htl,
        float* __restrict__ aggout,
        const float* __restrict__ pgam, const float* __restrict__ pbet,
        const float* __restrict__ psum, const float* __restrict__ psq) {
    constexpr int NK16 = (3 * K) / 16;
    constexpr int HALF = K / 2;
    constexpr int NQ   = NK16 * 2;
    extern __shared__ char smem[];
    __nv_bfloat16* As = (__nv_bfloat16*)smem;
    float* Qs = (float*)(smem + FB_QS);
    float* hs = (float*)(smem + FB_HS);   // [buf][c01][HPAD]
    int*   sl = (int*)(smem + FB_SL);

    int t = threadIdx.x, w = t >> 5, lane = t & 31;
    int n0 = blockIdx.x * NODE_G;
    int nend = min(n0 + NODE_G, NN);
    int p0 = g_off[n0];
    int p1 = g_off[nend];
    int ce = p1 - p0;
    if (ce <= 0) return;
    int ceM = min(ce, ECAP);
    int EW = (ceM + 15) >> 4;
    int eBase = w * EW;

    // 16B-aligned H slice: start at p0a, consumer offset hoff
    int p0a  = p0 & ~3;
    int hoff = p0 - p0a;
    int cnt4 = (ceM + hoff + 3) >> 2;   // 16B chunks per c-row (<= 97)

    u32 a_base = smem_u32(As);
    u32 b_base = smem_u32(smem + FB_BS);
    u32 h_base = smem_u32(hs);

    {
        const char* Wsrc = (const char*)Wl;
        for (int i = t; i < 128 * NQ; i += 512) {
            int r = i / NQ, q = i - r * NQ;
            cpasync16(b_base + (u32)(r * 400 + q * 16), Wsrc + (size_t)r * 384 + q * 16);
        }
        for (int i = t; i < 2 * cnt4; i += 512) {
            int c01 = (i >= cnt4) ? 1 : 0;
            int q = i - c01 * cnt4;
            cpasync16(h_base + (u32)((c01 * HPAD + q * 4) * 4),
                      Htl + (size_t)c01 * NE + p0a + q * 4);
        }
        cp_commit();
    }

    for (int idx = t; idx < MPAD * HALF; idx += 512) {
        int r = idx / HALF, kp = idx - r * HALF;
        int k = kp * 2;
        int n = n0 + r;
        float v0 = 0.f, v1 = 0.f;
        if (r < NODE_G && n < NN) {
            v0 = X[(size_t)n * K + k];
            v1 = X[(size_t)n * K + k + 1];
            if (BN) {
                v0 = bnrelu(v0, pgam[k], pbet[k], psum[k], psq[k]);
                v1 = bnrelu(v1, pgam[k + 1], pbet[k + 1], psum[k + 1], psq[k + 1]);
            }
        }
        __nv_bfloat16 h0 = __float2bfloat16(v0);
        __nv_bfloat16 h1 = __float2bfloat16(v1);
        __nv_bfloat16 l0 = __float2bfloat16(v0 - __bfloat162float(h0));
        __nv_bfloat16 l1 = __float2bfloat16(v1 - __bfloat162float(h1));
        u32 hp = (u32)__bfloat16_as_ushort(h0) | ((u32)__bfloat16_as_ushort(h1) << 16);
        u32 lp = (u32)__bfloat16_as_ushort(l0) | ((u32)__bfloat16_as_ushort(l1) << 16);
        u32* Arow = (u32*)As + r * 100;
        Arow[kp]            = hp;
        Arow[HALF + kp]     = hp;
        Arow[2 * HALF + kp] = lp;
    }
    for (int i = t; i < ceM; i += 512) sl[i] = g_psrc[p0 + i] - n0;

    int wm = (w & 1) * 48;
    int wn = (w >> 1) * 16;

    float2 eacc[EWMAX];
#pragma unroll
    for (int j = 0; j < EWMAX; j++) eacc[j] = make_float2(0.f, 0.f);

    for (int cb = 0; cb < 64; cb++) {
        int buf = cb & 1;
        cp_wait0();
        __syncthreads();

        float acc[3][2][4];
#pragma unroll
        for (int mi = 0; mi < 3; mi++)
#pragma unroll
            for (int jb = 0; jb < 2; jb++)
#pragma unroll
                for (int q = 0; q < 4; q++) acc[mi][jb][q] = 0.f;
#pragma unroll
        for (int ks = 0; ks < NK16; ks++) {
            int k0 = ks * 16;
            u32 a[3][4];
#pragma unroll
            for (int mi = 0; mi < 3; mi++) {
                u32 addr = a_base + (u32)(((wm + mi * 16 + (lane & 15)) * ASTRIDE +
                                            k0 + (lane >> 4) * 8) * 2);
                ldsm_x4(a[mi][0], a[mi][1], a[mi][2], a[mi][3], addr);
            }
            u32 b[2][2];
#pragma unroll
            for (int jb = 0; jb < 2; jb++) {
                u32 addr = b_base + (u32)(((wn + jb * 8 + (lane & 7)) * ASTRIDE +
                                            k0 + ((lane >> 3) & 1) * 8) * 2);
                ldsm_x2(b[jb][0], b[jb][1], addr);
            }
#pragma unroll
            for (int mi = 0; mi < 3; mi++)
#pragma unroll
                for (int jb = 0; jb < 2; jb++)
                    mma16816(acc[mi][jb], a[mi], b[jb]);
        }
        __syncthreads();

        if (cb < 63) {
            const char* Wn = (const char*)Wl + (size_t)(cb + 1) * 128 * 384;
            for (int i = t; i < 128 * NQ; i += 512) {
                int r = i / NQ, q = i - r * NQ;
                cpasync16(b_base + (u32)(r * 400 + q * 16), Wn + (size_t)r * 384 + q * 16);
            }
            const float* Hn = Htl + (size_t)(2 * (cb + 1)) * NE + p0a;
            u32 hdst = h_base + (u32)((buf ^ 1) * 2 * HPAD * 4);
            for (int i = t; i < 2 * cnt4; i += 512) {
                int c01 = (i >= cnt4) ? 1 : 0;
                int q = i - c01 * cnt4;
                cpasync16(hdst + (u32)((c01 * HPAD + q * 4) * 4),
                          Hn + (size_t)c01 * NE + q * 4);
            }
        }
        cp_commit();

#pragma unroll
        for (int mi = 0; mi < 3; mi++) {
            int m0 = wm + mi * 16 + (lane >> 2);
#pragma unroll
            for (int jb = 0; jb < 2; jb++) {
                int col = wn + jb * 8 + (lane & 3) * 2;
                if (m0 < NODE_G)
                    *(float2*)&Qs[m0 * QSTRIDE + col] = make_float2(acc[mi][jb][0], acc[mi][jb][1]);
                if (m0 + 8 < NODE_G)
                    *(float2*)&Qs[(m0 + 8) * QSTRIDE + col] = make_float2(acc[mi][jb][2], acc[mi][jb][3]);
            }
        }
        __syncthreads();

        {
            const float* hb0 = hs + buf * 2 * HPAD + hoff;
            const float* hb1 = hb0 + HPAD;
#pragma unroll
            for (int j = 0; j < EWMAX; j++) {
                int e = eBase + j;
                if (j < EW && e < ceM) {
                    int s = sl[e];
                    float h0 = hb0[e];
                    float h1 = hb1[e];
                    float2 q0 = *(const float2*)&Qs[s * QSTRIDE + 2 * lane];
                    float2 q1 = *(const float2*)&Qs[s * QSTRIDE + 64 + 2 * lane];
                    eacc[j].x += h0 * q0.x + h1 * q1.x;
                    eacc[j].y += h0 * q0.y + h1 * q1.y;
                }
            }
        }
        for (int e = ceM + w; e < ce; e += 16) {
            int p = p0 + e;
            float h0 = Htl[(size_t)(2 * cb) * NE + p];
            float h1 = Htl[(size_t)(2 * cb + 1) * NE + p];
            int sg = g_psrc[p];
            int s = sg - n0;
            int d = g_pdst[p];
            float2 q0 = *(const float2*)&Qs[s * QSTRIDE + 2 * lane];
            float2 q1 = *(const float2*)&Qs[s * QSTRIDE + 64 + 2 * lane];
            float ax = h0 * q0.x + h1 * q1.x;
            float ay = h0 * q0.y + h1 * q1.y;
            if (cb == 0) {
                ax += g_xb[(size_t)sg * 64 + 2 * lane];
                ay += g_xb[(size_t)sg * 64 + 2 * lane + 1];
            }
            atomicAdd(&aggout[(size_t)d * 64 + 2 * lane], ax);
            atomicAdd(&aggout[(size_t)d * 64 + 2 * lane + 1], ay);
        }
    }

#pragma unroll
    for (int j = 0; j < EWMAX; j++) {
        int e = eBase + j;
        if (j < EW && e < ceM) {
            int p = p0 + e;
            int d = g_pdst[p];
            int sg = n0 + sl[e];
            float2 xv = *(const float2*)&g_xb[(size_t)sg * 64 + 2 * lane];
            atomicAdd(&aggout[(size_t)d * 64 + 2 * lane],     eacc[j].x + xv.x);
            atomicAdd(&aggout[(size_t)d * 64 + 2 * lane + 1], eacc[j].y + xv.y);
        }
    }
}

// ---------------- batch norm stats ----------------
__global__ void k_bn_stats(const float* __restrict__ agg,
                           float* __restrict__ bsum, float* __restrict__ bsq) {
    int t = threadIdx.x;
    int o = t & 63, s = t >> 6;
    float sum = 0.f, sq = 0.f;
    for (int n = blockIdx.x * 4 + s; n < NN; n += gridDim.x * 4) {
        float v = agg[(size_t)n * 64 + o];
        sum += v; sq += v * v;
    }
    __shared__ float ssum[256], ssq[256];
    ssum[t] = sum; ssq[t] = sq;
    __syncthreads();
    if (t < 128) { ssum[t] += ssum[t + 128]; ssq[t] += ssq[t + 128]; }
    __syncthreads();
    if (t < 64) {
        atomicAdd(&bsum[t], ssum[t] + ssum[t + 64]);
        atomicAdd(&bsq [t], ssq [t] + ssq [t + 64]);
    }
}

// ---------------- pooling (BN-inline) + final MLP ----------------
__global__ void k_pool_init() {
    int i = blockIdx.x * blockDim.x + threadIdx.x;
    if (i < NG * HID) g_pool[i] = 0.f;
}
__global__ void k_pool(const float* __restrict__ agg,
                       const float* __restrict__ pgam, const float* __restrict__ pbet,
                       const float* __restrict__ psum, const float* __restrict__ psq,
                       const int* __restrict__ batch) {
    int i = blockIdx.x * blockDim.x + threadIdx.x;
    if (i >= NN * 64) return;
    int n = i >> 6, o = i & 63;
    float v = bnrelu(agg[i], pgam[o], pbet[o], psum[o], psq[o]);
    int g = batch[n];
    atomicMax(reinterpret_cast<unsigned int*>(&g_pool[g * 64 + o]), __float_as_uint(v));
}
__global__ void k_final(const float* __restrict__ u,
                        const float* __restrict__ w1, const float* __restrict__ b1,
                        const float* __restrict__ w2, const float* __restrict__ b2,
                        float* __restrict__ out) {
    int g = blockIdx.x;
    int j = threadIdx.x;
    __shared__ float cat[72];
    __shared__ float red[64];
    if (j < 64) cat[j] = g_pool[g * 64 + j];
    if (j < 8)  cat[64 + j] = u[g * 8 + j];
    __syncthreads();
    float h = b1[j];
#pragma unroll
    for (int k = 0; k < 72; k++) h += cat[k] * w1[k * 64 + j];
    h = fmaxf(h, 0.f);
    red[j] = h * w2[j];
    __syncthreads();
    for (int s = 32; s > 0; s >>= 1) {
        if (j < s) red[j] += red[j + s];
        __syncthreads();
    }
    if (j == 0) out[g] = red[0] + b2[0];
}

// ---------------- host ----------------
extern "C" void kernel_launch(void* const* d_in, const int* in_sizes, int n_in,
                              void* d_out, int out_size) {
    const float* x       = (const float*)d_in[0];
    const int*   ei      = (const int*)  d_in[1];
    const float* ea      = (const float*)d_in[2];
    const int*   batch   = (const int*)  d_in[3];
    const float* u       = (const float*)d_in[4];
    const float* enn0_w1 = (const float*)d_in[5];
    const float* enn0_b1 = (const float*)d_in[6];
    const float* enn0_w2 = (const float*)d_in[7];
    const float* enn0_b2 = (const float*)d_in[8];
    const float* root0   = (const float*)d_in[9];
    const float* bias0   = (const float*)d_in[10];
    const float* gamma0  = (const float*)d_in[11];
    const float* beta0   = (const float*)d_in[12];
    const float* enn_w1  = (const float*)d_in[13];
    const float* enn_b1  = (const float*)d_in[14];
    const float* enn_w2  = (const float*)d_in[15];
    const float* enn_b2  = (const float*)d_in[16];
    const float* root_l  = (const float*)d_in[17];
    const float* bias_l  = (const float*)d_in[18];
    const float* gamma_l = (const float*)d_in[19];
    const float* beta_l  = (const float*)d_in[20];
    const float* pp_w1   = (const float*)d_in[21];
    const float* pp_b1   = (const float*)d_in[22];
    const float* pp_w2   = (const float*)d_in[23];
    const float* pp_b2   = (const float*)d_in[24];

    const int* src  = ei;
    const int* dste = ei + NE;

    cudaFuncSetAttribute((void*)k_fused<IN_CH, false>, cudaFuncAttributeMaxDynamicSharedMemorySize, FB_TOTAL);
    cudaFuncSetAttribute((void*)k_fused<HID, true>,    cudaFuncAttributeMaxDynamicSharedMemorySize, FB_TOTAL);

    void* p;
    cudaGetSymbolAddress(&p, g_aggA);   float* aggA = (float*)p;
    cudaGetSymbolAddress(&p, g_aggB);   float* aggB = (float*)p;
    cudaGetSymbolAddress(&p, g_bnsum4); float* bns  = (float*)p;
    cudaGetSymbolAddress(&p, g_bnsq4);  float* bnq  = (float*)p;
    cudaGetSymbolAddress(&p, g_Wbf4);   __nv_bfloat16* Wbf = (__nv_bfloat16*)p;
    cudaGetSymbolAddress(&p, g_Ht4);    float* Ht   = (float*)p;

    k_zero_cnt<<<(NN + 255) / 256, 256>>>();
    k_count  <<<(NE + 255) / 256, 256>>>(src);
    k_scan   <<<1, 1024>>>();
    k_scatter<<<(NE + 255) / 256, 256>>>(src, dste);

    k_wsplit_all<<<512, 256>>>(enn0_w2, enn_w2);
    k_edgeh_all <<<4 * NEB, 128>>>(ea, enn0_w1, enn0_b1, enn_w1, enn_b1);

    const float* prev = x;
    const float* pgam = gamma0, *pbet = beta0;
    float* psum = bns, *psq = bnq;

    for (int l = 0; l < 4; l++) {
        int C = (l == 0) ? IN_CH : HID;
        const float *rt, *bs, *b2;
        if (l == 0) { rt = root0; bs = bias0; b2 = enn0_b2; }
        else {
            int m = l - 1;
            rt = root_l + (size_t)m * 64 * 64;
            bs = bias_l + (size_t)m * 64;
            b2 = enn_b2 + (size_t)m * 4096;
        }
        float* cur = (l & 1) ? aggB : aggA;
        float* sum_l = bns + l * 64;
        float* sq_l  = bnq + l * 64;

        k_node_pre<<<(NN + 3) / 4, 256>>>(prev, C, (l > 0) ? 1 : 0,
                                          pgam, pbet, psum, psq,
                                          cur, rt, bs, b2, sum_l, sq_l);
        __nv_bfloat16* Wl = Wbf + (size_t)l * 8192 * 192;
        float* Htl = Ht + (size_t)l * 128 * NE;
        if (l == 0)
            k_fused<IN_CH, false><<<148, 512, FB_TOTAL>>>(prev, Wl, Htl, cur,
                                                          pgam, pbet, psum, psq);
        else
            k_fused<HID, true><<<148, 512, FB_TOTAL>>>(prev, Wl, Htl, cur,
                                                       pgam, pbet, psum, psq);
        k_bn_stats<<<128, 256>>>(cur, sum_l, sq_l);

        prev = cur;
        if (l == 0) { pgam = gamma0; pbet = beta0; }
        else        { pgam = gamma_l + (size_t)(l - 1) * 64; pbet = beta_l + (size_t)(l - 1) * 64; }
        psum = sum_l; psq = sq_l;
    }

    k_pool_init<<<(NG * HID + 255) / 256, 256>>>();
    k_pool     <<<(NN * 64 + 255) / 256, 256>>>(prev,
                    gamma_l + 2 * 64, beta_l + 2 * 64, bns + 3 * 64, bnq + 3 * 64, batch);
    k_final    <<<NG, 64>>>(u, pp_w1, pp_b1, pp_w2, pp_b2, (float*)d_out);
}